// round 1
// baseline (speedup 1.0000x reference)
#include <cuda_runtime.h>
#include <math.h>

#define DMODEL 2048
#define NHEADS 16
#define HDIM   128
#define BATCH  2
#define SEQ    2048
#define MROWS  (BATCH*SEQ)            // 4096
#define BHS    (BATCH*NHEADS*SEQ)     // 65536 rows of HDIM

// ---------------- scratch (device globals: no allocations allowed) ----------
__device__ float g_q[BHS*HDIM];       // [B][H][S][D]
__device__ float g_k[BHS*HDIM];
__device__ float g_v[BHS*HDIM];
__device__ float g_att[MROWS*DMODEL]; // [B*S][H*D]
__device__ float g_cos[SEQ*64];
__device__ float g_sin[SEQ*64];

// ---------------- RoPE table (double precision, matches fp32 reference) -----
__global__ void rope_table_kernel() {
    int idx = blockIdx.x * 256 + threadIdx.x;
    if (idx >= SEQ * 64) return;
    int s = idx >> 6, p = idx & 63;
    double invf = pow(10000.0, -((double)(2 * p)) / 128.0);
    float invf_f = (float)invf;                  // reference rounds inv_freq to f32
    float ang = (float)s * invf_f;               // reference angle is f32 product
    g_cos[idx] = (float)cos((double)ang);
    g_sin[idx] = (float)sin((double)ang);
}

// ---------------- shared GEMM tile core: C[64x64] = A[64xK] * B[64xK]^T -----
// A,B both row-major with K contiguous (NT GEMM). 256 threads, 4x4 per thread,
// double-buffered SMEM, float4 compute loads (conflict-free).
__device__ __forceinline__ void gemm_tile_nt(const float* __restrict__ A,
                                             const float* __restrict__ B,
                                             int m0, int n0, float acc[4][4]) {
    __shared__ __align__(16) float As[2][16][68];
    __shared__ __align__(16) float Bs[2][16][68];
    const int tid = threadIdx.x;
    const int tx = tid & 15, ty = tid >> 4;
    const int lr = tid >> 2;           // 0..63 row within tile
    const int lc = (tid & 3) << 2;     // 0,4,8,12 k-offset

    const float* aptr = A + (size_t)(m0 + lr) * DMODEL + lc;
    const float* bptr = B + (size_t)(n0 + lr) * DMODEL + lc;

    float4 av = *(const float4*)aptr;
    float4 bv = *(const float4*)bptr;
    As[0][lc+0][lr] = av.x; As[0][lc+1][lr] = av.y;
    As[0][lc+2][lr] = av.z; As[0][lc+3][lr] = av.w;
    Bs[0][lc+0][lr] = bv.x; Bs[0][lc+1][lr] = bv.y;
    Bs[0][lc+2][lr] = bv.z; Bs[0][lc+3][lr] = bv.w;
    __syncthreads();

    int buf = 0;
    const int NT = DMODEL / 16;        // 128 k-tiles
    for (int kt = 1; kt <= NT; ++kt) {
        float4 an, bn;
        if (kt < NT) {                 // prefetch next tile to registers
            an = *(const float4*)(aptr + kt * 16);
            bn = *(const float4*)(bptr + kt * 16);
        }
#pragma unroll
        for (int kk = 0; kk < 16; ++kk) {
            float4 a4 = *(const float4*)&As[buf][kk][ty * 4];
            float4 b4 = *(const float4*)&Bs[buf][kk][tx * 4];
            float ar[4] = {a4.x, a4.y, a4.z, a4.w};
            float br[4] = {b4.x, b4.y, b4.z, b4.w};
#pragma unroll
            for (int i = 0; i < 4; ++i)
#pragma unroll
                for (int j = 0; j < 4; ++j)
                    acc[i][j] += ar[i] * br[j];
        }
        if (kt < NT) {
            int nb = buf ^ 1;
            As[nb][lc+0][lr] = an.x; As[nb][lc+1][lr] = an.y;
            As[nb][lc+2][lr] = an.z; As[nb][lc+3][lr] = an.w;
            Bs[nb][lc+0][lr] = bn.x; Bs[nb][lc+1][lr] = bn.y;
            Bs[nb][lc+2][lr] = bn.z; Bs[nb][lc+3][lr] = bn.w;
            __syncthreads();
            buf = nb;
        }
    }
}

// ---------------- fused QKV projection --------------------------------------
// grid (96, 64): x = n-tile across [wq|wk|wv], y = m-tile. Scatter epilogue
// writes directly into [B][H][S][D] layout.
__global__ __launch_bounds__(256) void gemm_qkv(const float* __restrict__ X,
                                                const float* __restrict__ Wq,
                                                const float* __restrict__ Wk,
                                                const float* __restrict__ Wv) {
    const int nt = blockIdx.x;         // 0..95
    const int which = nt >> 5;         // 0=q 1=k 2=v
    const int n0 = (nt & 31) * 64;
    const int m0 = blockIdx.y * 64;
    const float* W = (which == 0) ? Wq : (which == 1) ? Wk : Wv;

    float acc[4][4] = {};
    gemm_tile_nt(X, W, m0, n0, acc);

    float* OUT = (which == 0) ? g_q : (which == 1) ? g_k : g_v;
    const int tx = threadIdx.x & 15, ty = threadIdx.x >> 4;
#pragma unroll
    for (int i = 0; i < 4; ++i) {
        int m = m0 + ty * 4 + i;
        int b = m >> 11, s = m & 2047;
#pragma unroll
        for (int j = 0; j < 4; ++j) {
            int n = n0 + tx * 4 + j;
            int h = n >> 7, d = n & 127;
            OUT[(((size_t)b * NHEADS + h) * SEQ + s) * HDIM + d] = acc[i][j];
        }
    }
}

// ---------------- output projection -----------------------------------------
__global__ __launch_bounds__(256) void gemm_out(const float* __restrict__ Wo,
                                                float* __restrict__ C) {
    const int n0 = blockIdx.x * 64;
    const int m0 = blockIdx.y * 64;
    float acc[4][4] = {};
    gemm_tile_nt(g_att, Wo, m0, n0, acc);
    const int tx = threadIdx.x & 15, ty = threadIdx.x >> 4;
#pragma unroll
    for (int i = 0; i < 4; ++i) {
        int m = m0 + ty * 4 + i;
#pragma unroll
        for (int j = 0; j < 4; ++j)
            C[(size_t)m * DMODEL + n0 + tx * 4 + j] = acc[i][j];
    }
}

// ---------------- fused RoPE + per-head LayerNorm (in place on g_q/g_k) -----
__global__ __launch_bounds__(128) void rope_ln_kernel(const float* __restrict__ qw,
                                                      const float* __restrict__ kw) {
    int row  = blockIdx.x * 4 + (threadIdx.x >> 5);   // 0 .. 2*BHS-1
    int lane = threadIdx.x & 31;
    bool is_q = (row < BHS);
    int r2 = is_q ? row : row - BHS;
    float* base = is_q ? g_q : g_k;
    const float* w = is_q ? qw : kw;
    int s = r2 & (SEQ - 1);

    float* ptr = base + (size_t)r2 * HDIM + lane * 4;
    float4 v = *(float4*)ptr;
    int p0 = lane * 2, p1 = lane * 2 + 1;
    float c0 = g_cos[s * 64 + p0], s0 = g_sin[s * 64 + p0];
    float c1 = g_cos[s * 64 + p1], s1 = g_sin[s * 64 + p1];
    float o0 = v.x * c0 - v.y * s0;
    float o1 = v.x * s0 + v.y * c0;
    float o2 = v.z * c1 - v.w * s1;
    float o3 = v.z * s1 + v.w * c1;

    float sum = o0 + o1 + o2 + o3;
#pragma unroll
    for (int m = 16; m; m >>= 1) sum += __shfl_xor_sync(~0u, sum, m);
    float mu = sum * (1.0f / 128.0f);
    float d0 = o0 - mu, d1 = o1 - mu, d2 = o2 - mu, d3 = o3 - mu;
    float ss = d0 * d0 + d1 * d1 + d2 * d2 + d3 * d3;
#pragma unroll
    for (int m = 16; m; m >>= 1) ss += __shfl_xor_sync(~0u, ss, m);
    float rstd = rsqrtf(ss * (1.0f / 128.0f) + 1e-5f);

    float4 wv = *(const float4*)(w + lane * 4);
    v.x = d0 * rstd * wv.x; v.y = d1 * rstd * wv.y;
    v.z = d2 * rstd * wv.z; v.w = d3 * rstd * wv.w;
    *(float4*)ptr = v;
}

// ---------------- windowed flash attention ----------------------------------
// grid (B*H, S/64), 256 threads. Thread owns score rows {ty+16i}, score cols
// {tx+16j}, O cols {tx+16u} — spread indexing keeps SMEM conflict-free.
#define AQ 64
#define AK 64
#define KSTR 129
#define PSTR 65
#define ATTN_SMEM ((AQ*KSTR*3 + AQ*PSTR) * 4)   // 115712 B

__global__ __launch_bounds__(256) void attn_kernel(const int* __restrict__ wptr) {
    extern __shared__ float sm[];
    float* Qs = sm;
    float* Ks = Qs + AQ * KSTR;
    float* Vs = Ks + AK * KSTR;
    float* Ps = Vs + AK * KSTR;

    const int bh = blockIdx.x;
    const int q0 = blockIdx.y * AQ;
    const int W  = *wptr;
    const int tid = threadIdx.x;
    const int tx = tid & 15, ty = tid >> 4;

    const float* qbase = g_q + (size_t)bh * SEQ * HDIM;
    const float* kbase = g_k + (size_t)bh * SEQ * HDIM;
    const float* vbase = g_v + (size_t)bh * SEQ * HDIM;
    const float scale = 0.08838834764831845f;   // 1/sqrt(128)

    for (int idx = tid; idx < AQ * 32; idx += 256) {
        int r = idx >> 5, seg = (idx & 31) << 2;
        float4 qv = *(const float4*)(qbase + (size_t)(q0 + r) * HDIM + seg);
        Qs[r * KSTR + seg + 0] = qv.x * scale;
        Qs[r * KSTR + seg + 1] = qv.y * scale;
        Qs[r * KSTR + seg + 2] = qv.z * scale;
        Qs[r * KSTR + seg + 3] = qv.w * scale;
    }

    float o[4][8];
    float mrow[4], lrow[4];
#pragma unroll
    for (int i = 0; i < 4; ++i) {
        mrow[i] = -1e30f; lrow[i] = 0.f;
#pragma unroll
        for (int u = 0; u < 8; ++u) o[i][u] = 0.f;
    }

    int t0 = q0 - W; if (t0 < 0) t0 = 0; t0 &= ~63;

    for (int kt = t0; kt <= q0; kt += AK) {
        for (int idx = tid; idx < AK * 32; idx += 256) {
            int r = idx >> 5, seg = (idx & 31) << 2;
            float4 kv = *(const float4*)(kbase + (size_t)(kt + r) * HDIM + seg);
            float4 vv = *(const float4*)(vbase + (size_t)(kt + r) * HDIM + seg);
            Ks[r * KSTR + seg + 0] = kv.x; Ks[r * KSTR + seg + 1] = kv.y;
            Ks[r * KSTR + seg + 2] = kv.z; Ks[r * KSTR + seg + 3] = kv.w;
            Vs[r * KSTR + seg + 0] = vv.x; Vs[r * KSTR + seg + 1] = vv.y;
            Vs[r * KSTR + seg + 2] = vv.z; Vs[r * KSTR + seg + 3] = vv.w;
        }
        __syncthreads();

        float sc[4][4] = {};
#pragma unroll 4
        for (int k = 0; k < HDIM; ++k) {
            float a[4], b[4];
#pragma unroll
            for (int i = 0; i < 4; ++i) a[i] = Qs[(ty + 16 * i) * KSTR + k];
#pragma unroll
            for (int j = 0; j < 4; ++j) b[j] = Ks[(tx + 16 * j) * KSTR + k];
#pragma unroll
            for (int i = 0; i < 4; ++i)
#pragma unroll
                for (int j = 0; j < 4; ++j)
                    sc[i][j] += a[i] * b[j];
        }

#pragma unroll
        for (int i = 0; i < 4; ++i) {
            int qg = q0 + ty + 16 * i;
            float tmax = -1e30f;
            bool valid[4];
#pragma unroll
            for (int j = 0; j < 4; ++j) {
                int kg = kt + tx + 16 * j;
                valid[j] = (kg <= qg) && (kg >= qg - W);
                if (valid[j]) tmax = fmaxf(tmax, sc[i][j]);
            }
#pragma unroll
            for (int m = 8; m; m >>= 1)
                tmax = fmaxf(tmax, __shfl_xor_sync(~0u, tmax, m));
            float mnew = fmaxf(mrow[i], tmax);
            float alpha = __expf(mrow[i] - mnew);
            mrow[i] = mnew;
            lrow[i] *= alpha;
#pragma unroll
            for (int j = 0; j < 4; ++j) {
                float p = valid[j] ? __expf(sc[i][j] - mnew) : 0.f;
                lrow[i] += p;
                Ps[(ty + 16 * i) * PSTR + tx + 16 * j] = p;
            }
#pragma unroll
            for (int u = 0; u < 8; ++u) o[i][u] *= alpha;
        }
        __syncthreads();

#pragma unroll 4
        for (int kk = 0; kk < AK; ++kk) {
            float p[4], vv[8];
#pragma unroll
            for (int i = 0; i < 4; ++i) p[i] = Ps[(ty + 16 * i) * PSTR + kk];
#pragma unroll
            for (int u = 0; u < 8; ++u) vv[u] = Vs[kk * KSTR + tx + 16 * u];
#pragma unroll
            for (int i = 0; i < 4; ++i)
#pragma unroll
                for (int u = 0; u < 8; ++u)
                    o[i][u] += p[i] * vv[u];
        }
        __syncthreads();
    }

    const int b = bh >> 4, h = bh & 15;
#pragma unroll
    for (int i = 0; i < 4; ++i) {
        float lsum = lrow[i];
#pragma unroll
        for (int m = 8; m; m >>= 1) lsum += __shfl_xor_sync(~0u, lsum, m);
        float inv = 1.0f / lsum;
        int sg = q0 + ty + 16 * i;
        float* orow = g_att + ((size_t)(b * SEQ + sg)) * DMODEL + h * HDIM;
#pragma unroll
        for (int u = 0; u < 8; ++u) orow[tx + 16 * u] = o[i][u] * inv;
    }
}

// ---------------- launch -----------------------------------------------------
extern "C" void kernel_launch(void* const* d_in, const int* in_sizes, int n_in,
                              void* d_out, int out_size) {
    const float* x   = (const float*)d_in[0];
    const float* wq  = (const float*)d_in[1];
    const float* wk  = (const float*)d_in[2];
    const float* wv  = (const float*)d_in[3];
    const float* wo  = (const float*)d_in[4];
    const float* qnw = (const float*)d_in[5];
    const float* knw = (const float*)d_in[6];
    const int*   wsz = (const int*)d_in[7];
    (void)in_sizes; (void)n_in; (void)out_size;

    rope_table_kernel<<<(SEQ * 64 + 255) / 256, 256>>>();
    gemm_qkv<<<dim3(96, MROWS / 64), 256>>>(x, wq, wk, wv);
    rope_ln_kernel<<<(2 * BHS) / 4, 128>>>(qnw, knw);
    cudaFuncSetAttribute(attn_kernel,
                         cudaFuncAttributeMaxDynamicSharedMemorySize, ATTN_SMEM);
    attn_kernel<<<dim3(BATCH * NHEADS, SEQ / 64), 256, ATTN_SMEM>>>(wsz);
    gemm_out<<<dim3(DMODEL / 64, MROWS / 64), 256>>>(wo, (float*)d_out);
}

// round 2
// speedup vs baseline: 1.0184x; 1.0184x over previous
#include <cuda_runtime.h>
#include <math.h>

#define DMODEL 2048
#define NHEADS 16
#define HDIM   128
#define BATCH  2
#define SEQ    2048
#define MROWS  (BATCH*SEQ)            // 4096
#define BHS    (BATCH*NHEADS*SEQ)     // 65536 rows of HDIM

typedef unsigned long long u64t;

// ---------------- f32x2 packed-math helpers (sm_103a FFMA2 path) ------------
__device__ __forceinline__ u64t ffma2(u64t a, u64t b, u64t c) {
    u64t d; asm("fma.rn.f32x2 %0,%1,%2,%3;" : "=l"(d) : "l"(a), "l"(b), "l"(c));
    return d;
}
__device__ __forceinline__ u64t fmul2(u64t a, u64t b) {
    u64t d; asm("mul.rn.f32x2 %0,%1,%2;" : "=l"(d) : "l"(a), "l"(b));
    return d;
}
__device__ __forceinline__ u64t fdup2(float x) {
    u64t d; asm("mov.b64 %0,{%1,%1};" : "=l"(d) : "f"(x));
    return d;
}
__device__ __forceinline__ float2 funpack(u64t d) {
    float2 r; asm("mov.b64 {%0,%1},%2;" : "=f"(r.x), "=f"(r.y) : "l"(d));
    return r;
}

// ---------------- scratch (device globals: no allocations allowed) ----------
__device__ float g_q[BHS*HDIM];       // [B][H][S][D]
__device__ float g_k[BHS*HDIM];
__device__ float g_v[BHS*HDIM];
__device__ float g_att[MROWS*DMODEL]; // [B*S][H*D]
__device__ float g_cos[SEQ*64];
__device__ float g_sin[SEQ*64];

// ---------------- RoPE table (double precision, matches fp32 reference) -----
__global__ void rope_table_kernel() {
    int idx = blockIdx.x * 256 + threadIdx.x;
    if (idx >= SEQ * 64) return;
    int s = idx >> 6, p = idx & 63;
    double invf = pow(10000.0, -((double)(2 * p)) / 128.0);
    float invf_f = (float)invf;                  // reference rounds inv_freq to f32
    float ang = (float)s * invf_f;               // reference angle is f32 product
    g_cos[idx] = (float)cos((double)ang);
    g_sin[idx] = (float)sin((double)ang);
}

// ---------------- GEMM tile core with FFMA2: C[64x64] = A[64xK]*B[64xK]^T ---
// acc2[ip][j] holds row-pairs (m = ty*4+2ip+{0,1}) packed in f32x2 lanes.
__device__ __forceinline__ void gemm_tile_nt(const float* __restrict__ A,
                                             const float* __restrict__ B,
                                             int m0, int n0, u64t acc2[2][4]) {
    __shared__ __align__(16) float As[2][16][68];
    __shared__ __align__(16) float Bs[2][16][68];
    const int tid = threadIdx.x;
    const int tx = tid & 15, ty = tid >> 4;
    const int lr = tid >> 2;           // 0..63 row within tile
    const int lc = (tid & 3) << 2;     // 0,4,8,12 k-offset

    const float* aptr = A + (size_t)(m0 + lr) * DMODEL + lc;
    const float* bptr = B + (size_t)(n0 + lr) * DMODEL + lc;

    float4 av = *(const float4*)aptr;
    float4 bv = *(const float4*)bptr;
    As[0][lc+0][lr] = av.x; As[0][lc+1][lr] = av.y;
    As[0][lc+2][lr] = av.z; As[0][lc+3][lr] = av.w;
    Bs[0][lc+0][lr] = bv.x; Bs[0][lc+1][lr] = bv.y;
    Bs[0][lc+2][lr] = bv.z; Bs[0][lc+3][lr] = bv.w;
    __syncthreads();

    int buf = 0;
    const int NT = DMODEL / 16;        // 128 k-tiles
    for (int kt = 1; kt <= NT; ++kt) {
        float4 an, bn;
        if (kt < NT) {                 // prefetch next tile to registers
            an = *(const float4*)(aptr + kt * 16);
            bn = *(const float4*)(bptr + kt * 16);
        }
#pragma unroll
        for (int kk = 0; kk < 16; ++kk) {
            u64t a01 = *(const u64t*)&As[buf][kk][ty * 4];
            u64t a23 = *(const u64t*)&As[buf][kk][ty * 4 + 2];
            float4 b4 = *(const float4*)&Bs[buf][kk][tx * 4];
            u64t bd0 = fdup2(b4.x), bd1 = fdup2(b4.y);
            u64t bd2 = fdup2(b4.z), bd3 = fdup2(b4.w);
            acc2[0][0] = ffma2(a01, bd0, acc2[0][0]);
            acc2[1][0] = ffma2(a23, bd0, acc2[1][0]);
            acc2[0][1] = ffma2(a01, bd1, acc2[0][1]);
            acc2[1][1] = ffma2(a23, bd1, acc2[1][1]);
            acc2[0][2] = ffma2(a01, bd2, acc2[0][2]);
            acc2[1][2] = ffma2(a23, bd2, acc2[1][2]);
            acc2[0][3] = ffma2(a01, bd3, acc2[0][3]);
            acc2[1][3] = ffma2(a23, bd3, acc2[1][3]);
        }
        if (kt < NT) {
            int nb = buf ^ 1;
            As[nb][lc+0][lr] = an.x; As[nb][lc+1][lr] = an.y;
            As[nb][lc+2][lr] = an.z; As[nb][lc+3][lr] = an.w;
            Bs[nb][lc+0][lr] = bn.x; Bs[nb][lc+1][lr] = bn.y;
            Bs[nb][lc+2][lr] = bn.z; Bs[nb][lc+3][lr] = bn.w;
            __syncthreads();
            buf = nb;
        }
    }
}

// ---------------- fused QKV projection --------------------------------------
__global__ __launch_bounds__(256) void gemm_qkv(const float* __restrict__ X,
                                                const float* __restrict__ Wq,
                                                const float* __restrict__ Wk,
                                                const float* __restrict__ Wv) {
    const int nt = blockIdx.x;         // 0..95
    const int which = nt >> 5;         // 0=q 1=k 2=v
    const int n0 = (nt & 31) * 64;
    const int m0 = blockIdx.y * 64;
    const float* W = (which == 0) ? Wq : (which == 1) ? Wk : Wv;

    u64t acc2[2][4] = {};
    gemm_tile_nt(X, W, m0, n0, acc2);

    float* OUT = (which == 0) ? g_q : (which == 1) ? g_k : g_v;
    const int tx = threadIdx.x & 15, ty = threadIdx.x >> 4;
#pragma unroll
    for (int ip = 0; ip < 2; ++ip) {
#pragma unroll
        for (int j = 0; j < 4; ++j) {
            float2 t = funpack(acc2[ip][j]);
            int n = n0 + tx * 4 + j;
            int h = n >> 7, d = n & 127;
            int m = m0 + ty * 4 + 2 * ip;
            int b = m >> 11, s = m & 2047;
            OUT[(((size_t)b * NHEADS + h) * SEQ + s) * HDIM + d] = t.x;
            int m2 = m + 1;
            int b2 = m2 >> 11, s2 = m2 & 2047;
            OUT[(((size_t)b2 * NHEADS + h) * SEQ + s2) * HDIM + d] = t.y;
        }
    }
}

// ---------------- output projection -----------------------------------------
__global__ __launch_bounds__(256) void gemm_out(const float* __restrict__ Wo,
                                                float* __restrict__ C) {
    const int n0 = blockIdx.x * 64;
    const int m0 = blockIdx.y * 64;
    u64t acc2[2][4] = {};
    gemm_tile_nt(g_att, Wo, m0, n0, acc2);
    const int tx = threadIdx.x & 15, ty = threadIdx.x >> 4;
#pragma unroll
    for (int ip = 0; ip < 2; ++ip) {
#pragma unroll
        for (int j = 0; j < 4; ++j) {
            float2 t = funpack(acc2[ip][j]);
            int m = m0 + ty * 4 + 2 * ip;
            int n = n0 + tx * 4 + j;
            C[(size_t)m * DMODEL + n] = t.x;
            C[(size_t)(m + 1) * DMODEL + n] = t.y;
        }
    }
}

// ---------------- fused RoPE + per-head LayerNorm (in place on g_q/g_k) -----
__global__ __launch_bounds__(128) void rope_ln_kernel(const float* __restrict__ qw,
                                                      const float* __restrict__ kw) {
    int row  = blockIdx.x * 4 + (threadIdx.x >> 5);   // 0 .. 2*BHS-1
    int lane = threadIdx.x & 31;
    bool is_q = (row < BHS);
    int r2 = is_q ? row : row - BHS;
    float* base = is_q ? g_q : g_k;
    const float* w = is_q ? qw : kw;
    int s = r2 & (SEQ - 1);

    float* ptr = base + (size_t)r2 * HDIM + lane * 4;
    float4 v = *(float4*)ptr;
    int p0 = lane * 2, p1 = lane * 2 + 1;
    float c0 = g_cos[s * 64 + p0], s0 = g_sin[s * 64 + p0];
    float c1 = g_cos[s * 64 + p1], s1 = g_sin[s * 64 + p1];
    float o0 = v.x * c0 - v.y * s0;
    float o1 = v.x * s0 + v.y * c0;
    float o2 = v.z * c1 - v.w * s1;
    float o3 = v.z * s1 + v.w * c1;

    float sum = o0 + o1 + o2 + o3;
#pragma unroll
    for (int m = 16; m; m >>= 1) sum += __shfl_xor_sync(~0u, sum, m);
    float mu = sum * (1.0f / 128.0f);
    float d0 = o0 - mu, d1 = o1 - mu, d2 = o2 - mu, d3 = o3 - mu;
    float ss = d0 * d0 + d1 * d1 + d2 * d2 + d3 * d3;
#pragma unroll
    for (int m = 16; m; m >>= 1) ss += __shfl_xor_sync(~0u, ss, m);
    float rstd = rsqrtf(ss * (1.0f / 128.0f) + 1e-5f);

    float4 wv = *(const float4*)(w + lane * 4);
    v.x = d0 * rstd * wv.x; v.y = d1 * rstd * wv.y;
    v.z = d2 * rstd * wv.z; v.w = d3 * rstd * wv.w;
    *(float4*)ptr = v;
}

// ---------------- windowed flash attention (AQ=128, 512 threads, f32x2) -----
// Score tile 128x64: thread rows ty+32i, cols tx+16j. O cols 2*tx+32u (pairs).
#define AQ 128
#define AK 64
#define KSTR 130
#define PSTR 66
#define ATTN_SMEM ((AQ*KSTR + 2*AK*KSTR + AQ*PSTR) * 4)   // 166912 B

__global__ __launch_bounds__(512) void attn_kernel(const int* __restrict__ wptr) {
    extern __shared__ float sm[];
    float* Qs = sm;                       // [AQ][KSTR]
    float* Ks = Qs + AQ * KSTR;           // [AK][KSTR]
    float* Vs = Ks + AK * KSTR;           // [AK][KSTR]
    float* Ps = Vs + AK * KSTR;           // [AQ][PSTR]

    const int bh = blockIdx.x;
    const int q0 = blockIdx.y * AQ;
    const int W  = *wptr;
    const int tid = threadIdx.x;
    const int tx = tid & 15, ty = tid >> 4;      // ty 0..31

    const float* qbase = g_q + (size_t)bh * SEQ * HDIM;
    const float* kbase = g_k + (size_t)bh * SEQ * HDIM;
    const float* vbase = g_v + (size_t)bh * SEQ * HDIM;
    const float scale = 0.08838834764831845f;    // 1/sqrt(128)

    for (int idx = tid; idx < AQ * 32; idx += 512) {
        int r = idx >> 5, seg = (idx & 31) << 2;
        float4 qv = *(const float4*)(qbase + (size_t)(q0 + r) * HDIM + seg);
        Qs[r * KSTR + seg + 0] = qv.x * scale;
        Qs[r * KSTR + seg + 1] = qv.y * scale;
        Qs[r * KSTR + seg + 2] = qv.z * scale;
        Qs[r * KSTR + seg + 3] = qv.w * scale;
    }

    u64t o2[4][4];                       // col-pairs, f32x2
    float mrow[4], lrow[4];
#pragma unroll
    for (int i = 0; i < 4; ++i) {
        mrow[i] = -1e30f; lrow[i] = 0.f;
#pragma unroll
        for (int u = 0; u < 4; ++u) o2[i][u] = 0ull;
    }

    int t0 = q0 - W; if (t0 < 0) t0 = 0; t0 &= ~(AK - 1);
    const int tend = q0 + AQ - AK;

    for (int kt = t0; kt <= tend; kt += AK) {
        for (int idx = tid; idx < AK * 32; idx += 512) {
            int r = idx >> 5, seg = (idx & 31) << 2;
            float4 kv = *(const float4*)(kbase + (size_t)(kt + r) * HDIM + seg);
            float4 vv = *(const float4*)(vbase + (size_t)(kt + r) * HDIM + seg);
            Ks[r * KSTR + seg + 0] = kv.x; Ks[r * KSTR + seg + 1] = kv.y;
            Ks[r * KSTR + seg + 2] = kv.z; Ks[r * KSTR + seg + 3] = kv.w;
            Vs[r * KSTR + seg + 0] = vv.x; Vs[r * KSTR + seg + 1] = vv.y;
            Vs[r * KSTR + seg + 2] = vv.z; Vs[r * KSTR + seg + 3] = vv.w;
        }
        __syncthreads();

        // QK^T: packed over k-pairs (lanes = even/odd k partial sums)
        u64t sc2[4][4] = {};
#pragma unroll 2
        for (int k = 0; k < HDIM; k += 2) {
            u64t a2[4], b2[4];
#pragma unroll
            for (int i = 0; i < 4; ++i)
                a2[i] = *(const u64t*)&Qs[(ty + 32 * i) * KSTR + k];
#pragma unroll
            for (int j = 0; j < 4; ++j)
                b2[j] = *(const u64t*)&Ks[(tx + 16 * j) * KSTR + k];
#pragma unroll
            for (int i = 0; i < 4; ++i)
#pragma unroll
                for (int j = 0; j < 4; ++j)
                    sc2[i][j] = ffma2(a2[i], b2[j], sc2[i][j]);
        }
        float sc[4][4];
#pragma unroll
        for (int i = 0; i < 4; ++i)
#pragma unroll
            for (int j = 0; j < 4; ++j) {
                float2 t = funpack(sc2[i][j]);
                sc[i][j] = t.x + t.y;
            }

#pragma unroll
        for (int i = 0; i < 4; ++i) {
            int qg = q0 + ty + 32 * i;
            float tmax = -1e30f;
            bool valid[4];
#pragma unroll
            for (int j = 0; j < 4; ++j) {
                int kg = kt + tx + 16 * j;
                valid[j] = (kg <= qg) && (kg >= qg - W);
                if (valid[j]) tmax = fmaxf(tmax, sc[i][j]);
            }
#pragma unroll
            for (int m = 8; m; m >>= 1)
                tmax = fmaxf(tmax, __shfl_xor_sync(~0u, tmax, m));
            float mnew = fmaxf(mrow[i], tmax);
            float alpha = __expf(mrow[i] - mnew);
            mrow[i] = mnew;
            lrow[i] *= alpha;
#pragma unroll
            for (int j = 0; j < 4; ++j) {
                float p = valid[j] ? __expf(sc[i][j] - mnew) : 0.f;
                lrow[i] += p;
                Ps[(ty + 32 * i) * PSTR + tx + 16 * j] = p;
            }
            u64t al2 = fdup2(alpha);
#pragma unroll
            for (int u = 0; u < 4; ++u) o2[i][u] = fmul2(o2[i][u], al2);
        }
        __syncthreads();

        // P @ V: f32x2 lanes = column pairs (c = 2*tx + 32*u)
#pragma unroll 2
        for (int kk = 0; kk < AK; ++kk) {
            u64t pd[4], v2[4];
#pragma unroll
            for (int i = 0; i < 4; ++i)
                pd[i] = fdup2(Ps[(ty + 32 * i) * PSTR + kk]);
#pragma unroll
            for (int u = 0; u < 4; ++u)
                v2[u] = *(const u64t*)&Vs[kk * KSTR + 2 * tx + 32 * u];
#pragma unroll
            for (int i = 0; i < 4; ++i)
#pragma unroll
                for (int u = 0; u < 4; ++u)
                    o2[i][u] = ffma2(pd[i], v2[u], o2[i][u]);
        }
        __syncthreads();
    }

    const int b = bh >> 4, h = bh & 15;
#pragma unroll
    for (int i = 0; i < 4; ++i) {
        float lsum = lrow[i];
#pragma unroll
        for (int m = 8; m; m >>= 1) lsum += __shfl_xor_sync(~0u, lsum, m);
        float inv = 1.0f / lsum;
        int sg = q0 + ty + 32 * i;
        float* orow = g_att + ((size_t)(b * SEQ + sg)) * DMODEL + h * HDIM;
#pragma unroll
        for (int u = 0; u < 4; ++u) {
            float2 t = funpack(o2[i][u]);
            float2 w2 = make_float2(t.x * inv, t.y * inv);
            *(float2*)(orow + 2 * tx + 32 * u) = w2;
        }
    }
}

// ---------------- launch -----------------------------------------------------
extern "C" void kernel_launch(void* const* d_in, const int* in_sizes, int n_in,
                              void* d_out, int out_size) {
    const float* x   = (const float*)d_in[0];
    const float* wq  = (const float*)d_in[1];
    const float* wk  = (const float*)d_in[2];
    const float* wv  = (const float*)d_in[3];
    const float* wo  = (const float*)d_in[4];
    const float* qnw = (const float*)d_in[5];
    const float* knw = (const float*)d_in[6];
    const int*   wsz = (const int*)d_in[7];
    (void)in_sizes; (void)n_in; (void)out_size;

    rope_table_kernel<<<(SEQ * 64 + 255) / 256, 256>>>();
    gemm_qkv<<<dim3(96, MROWS / 64), 256>>>(x, wq, wk, wv);
    rope_ln_kernel<<<(2 * BHS) / 4, 128>>>(qnw, knw);
    cudaFuncSetAttribute(attn_kernel,
                         cudaFuncAttributeMaxDynamicSharedMemorySize, ATTN_SMEM);
    attn_kernel<<<dim3(BATCH * NHEADS, SEQ / AQ), 512, ATTN_SMEM>>>(wsz);
    gemm_out<<<dim3(DMODEL / 64, MROWS / 64), 256>>>(wo, (float*)d_out);
}

// round 5
// speedup vs baseline: 1.8128x; 1.7802x over previous
#include <cuda_runtime.h>
#include <cuda_bf16.h>
#include <math.h>
#include <stdint.h>

#define DMODEL 2048
#define NHEADS 16
#define HDIM   128
#define BATCH  2
#define SEQ    2048
#define MROWS  (BATCH*SEQ)            // 4096
#define BHS    (BATCH*NHEADS*SEQ)     // 65536 rows of HDIM

typedef unsigned long long u64t;

// ---------------- f32x2 helpers (attention kernel) --------------------------
__device__ __forceinline__ u64t ffma2(u64t a, u64t b, u64t c) {
    u64t d; asm("fma.rn.f32x2 %0,%1,%2,%3;" : "=l"(d) : "l"(a), "l"(b), "l"(c));
    return d;
}
__device__ __forceinline__ u64t fmul2(u64t a, u64t b) {
    u64t d; asm("mul.rn.f32x2 %0,%1,%2;" : "=l"(d) : "l"(a), "l"(b));
    return d;
}
__device__ __forceinline__ u64t fdup2(float x) {
    u64t d; asm("mov.b64 %0,{%1,%1};" : "=l"(d) : "f"(x));
    return d;
}
__device__ __forceinline__ float2 funpack(u64t d) {
    float2 r; asm("mov.b64 {%0,%1},%2;" : "=f"(r.x), "=f"(r.y) : "l"(d));
    return r;
}

// ---------------- generic-PTX tensor core helpers ---------------------------
__device__ __forceinline__ uint32_t smem_u32(const void* p) {
    uint32_t a;
    asm("{ .reg .u64 t; cvta.to.shared.u64 t, %1; cvt.u32.u64 %0, t; }"
        : "=r"(a) : "l"(p));
    return a;
}
__device__ __forceinline__ void ldm_x4(uint32_t r[4], uint32_t addr) {
    asm volatile("ldmatrix.sync.aligned.m8n8.x4.shared.b16 {%0,%1,%2,%3}, [%4];"
        : "=r"(r[0]), "=r"(r[1]), "=r"(r[2]), "=r"(r[3]) : "r"(addr));
}
__device__ __forceinline__ void ldm_x2(uint32_t r[2], uint32_t addr) {
    asm volatile("ldmatrix.sync.aligned.m8n8.x2.shared.b16 {%0,%1}, [%2];"
        : "=r"(r[0]), "=r"(r[1]) : "r"(addr));
}
__device__ __forceinline__ void mma_bf16(float c[4], const uint32_t a[4],
                                         const uint32_t b[2]) {
    asm volatile(
        "mma.sync.aligned.m16n8k16.row.col.f32.bf16.bf16.f32 "
        "{%0,%1,%2,%3}, {%4,%5,%6,%7}, {%8,%9}, {%0,%1,%2,%3};"
        : "+f"(c[0]), "+f"(c[1]), "+f"(c[2]), "+f"(c[3])
        : "r"(a[0]), "r"(a[1]), "r"(a[2]), "r"(a[3]), "r"(b[0]), "r"(b[1]));
}

// ---------------- scratch ----------------------------------------------------
__device__ float g_q[BHS*HDIM];       // [B][H][S][D]
__device__ float g_k[BHS*HDIM];
__device__ float g_v[BHS*HDIM];
__device__ float g_att[MROWS*DMODEL]; // [B*S][H*D]
__device__ float g_cos[SEQ*64];
__device__ float g_sin[SEQ*64];

// ---------------- RoPE table -------------------------------------------------
__global__ void rope_table_kernel() {
    int idx = blockIdx.x * 256 + threadIdx.x;
    if (idx >= SEQ * 64) return;
    int s = idx >> 6, p = idx & 63;
    double invf = pow(10000.0, -((double)(2 * p)) / 128.0);
    float invf_f = (float)invf;
    float ang = (float)s * invf_f;
    g_cos[idx] = (float)cos((double)ang);
    g_sin[idx] = (float)sin((double)ang);
}

// ---------------- tensor-core GEMM: 128x128 tile, NT, bf16 hi/lo split ------
// mode 0: A=x, B in {Wq,Wk,Wv} by n-range, scatter to g_q/g_k/g_v [B][H][S][D]
// mode 1: A=g_att (device symbol, resolved IN-KERNEL), B=W0, write Cout
#define KC 32
#define NCHUNK (DMODEL/KC)     // 64
#define ASTR 40                // padded bf16 stride (conflict-free ldmatrix)

__global__ __launch_bounds__(256) void gemm_mma(
        const float* __restrict__ Ain,
        const float* __restrict__ W0, const float* __restrict__ W1,
        const float* __restrict__ W2, float* __restrict__ Cout, int mode) {
    __shared__ __align__(16) __nv_bfloat16 sAh[128*ASTR], sAl[128*ASTR];
    __shared__ __align__(16) __nv_bfloat16 sBh[128*ASTR], sBl[128*ASTR];

    const int tid = threadIdx.x;
    const int lane = tid & 31, wid = tid >> 5;
    const int warpM = (wid >> 2) * 64;          // 0 / 64
    const int warpN = (wid & 3) * 32;           // 0..96

    const int m0  = blockIdx.y * 128;
    const int n0g = blockIdx.x * 128;
    // FIX R5: resolve g_att inside device code (host-side symbol arg was UB)
    const float* Ag = (mode == 1) ? (const float*)g_att : Ain;
    const float* Bg;
    int n0;
    if (mode == 0) {
        int which = n0g >> 11;
        Bg = (which == 0) ? W0 : (which == 1) ? W1 : W2;
        n0 = n0g & 2047;
    } else { Bg = W0; n0 = n0g; }

    const uint32_t sAh_b = smem_u32(sAh), sAl_b = smem_u32(sAl);
    const uint32_t sBh_b = smem_u32(sBh), sBl_b = smem_u32(sBl);

    float4 apre[4], bpre[4];

#define LOAD_CHUNK(c0) do {                                                    \
    _Pragma("unroll")                                                          \
    for (int i = 0; i < 4; ++i) {                                              \
        int idx = tid + 256 * i;                                               \
        int r = idx >> 3, kq = (idx & 7) << 2;                                 \
        apre[i] = *(const float4*)(Ag + (size_t)(m0 + r) * DMODEL + (c0) + kq);\
        bpre[i] = *(const float4*)(Bg + (size_t)(n0 + r) * DMODEL + (c0) + kq);\
    } } while (0)

#define STORE_CHUNK() do {                                                     \
    _Pragma("unroll")                                                          \
    for (int i = 0; i < 4; ++i) {                                              \
        int idx = tid + 256 * i;                                               \
        int r = idx >> 3, kq = (idx & 7) << 2;                                 \
        float4 f = apre[i];                                                    \
        __nv_bfloat16 h0=__float2bfloat16_rn(f.x), h1=__float2bfloat16_rn(f.y);\
        __nv_bfloat16 h2=__float2bfloat16_rn(f.z), h3=__float2bfloat16_rn(f.w);\
        __nv_bfloat16 l0=__float2bfloat16_rn(f.x-__bfloat162float(h0));        \
        __nv_bfloat16 l1=__float2bfloat16_rn(f.y-__bfloat162float(h1));        \
        __nv_bfloat16 l2=__float2bfloat16_rn(f.z-__bfloat162float(h2));        \
        __nv_bfloat16 l3=__float2bfloat16_rn(f.w-__bfloat162float(h3));        \
        *(uint2*)&sAh[r*ASTR+kq] = make_uint2(                                 \
            (uint32_t)__bfloat16_as_ushort(h0)|((uint32_t)__bfloat16_as_ushort(h1)<<16), \
            (uint32_t)__bfloat16_as_ushort(h2)|((uint32_t)__bfloat16_as_ushort(h3)<<16)); \
        *(uint2*)&sAl[r*ASTR+kq] = make_uint2(                                 \
            (uint32_t)__bfloat16_as_ushort(l0)|((uint32_t)__bfloat16_as_ushort(l1)<<16), \
            (uint32_t)__bfloat16_as_ushort(l2)|((uint32_t)__bfloat16_as_ushort(l3)<<16)); \
        f = bpre[i];                                                           \
        h0=__float2bfloat16_rn(f.x); h1=__float2bfloat16_rn(f.y);              \
        h2=__float2bfloat16_rn(f.z); h3=__float2bfloat16_rn(f.w);              \
        l0=__float2bfloat16_rn(f.x-__bfloat162float(h0));                      \
        l1=__float2bfloat16_rn(f.y-__bfloat162float(h1));                      \
        l2=__float2bfloat16_rn(f.z-__bfloat162float(h2));                      \
        l3=__float2bfloat16_rn(f.w-__bfloat162float(h3));                      \
        *(uint2*)&sBh[r*ASTR+kq] = make_uint2(                                 \
            (uint32_t)__bfloat16_as_ushort(h0)|((uint32_t)__bfloat16_as_ushort(h1)<<16), \
            (uint32_t)__bfloat16_as_ushort(h2)|((uint32_t)__bfloat16_as_ushort(h3)<<16)); \
        *(uint2*)&sBl[r*ASTR+kq] = make_uint2(                                 \
            (uint32_t)__bfloat16_as_ushort(l0)|((uint32_t)__bfloat16_as_ushort(l1)<<16), \
            (uint32_t)__bfloat16_as_ushort(l2)|((uint32_t)__bfloat16_as_ushort(l3)<<16)); \
    } } while (0)

    LOAD_CHUNK(0);
    STORE_CHUNK();
    __syncthreads();

    float acc[4][4][4];
#pragma unroll
    for (int mt = 0; mt < 4; ++mt)
#pragma unroll
        for (int nt = 0; nt < 4; ++nt)
#pragma unroll
            for (int q = 0; q < 4; ++q) acc[mt][nt][q] = 0.f;

    const uint32_t aoff = (uint32_t)(((warpM + (lane & 15)) * ASTR
                                      + (lane >> 4) * 8) * 2);
    const uint32_t boff = (uint32_t)(((warpN + (lane & 7)) * ASTR
                                      + ((lane >> 3) & 1) * 8) * 2);

    for (int c = 0; c < NCHUNK; ++c) {
        if (c + 1 < NCHUNK) LOAD_CHUNK((c + 1) * KC);

#pragma unroll
        for (int ks = 0; ks < 2; ++ks) {
            const uint32_t kb = ks * 32;       // 16 elems * 2B
            uint32_t ah[4][4], al[4][4], bh[4][2], bl[4][2];
#pragma unroll
            for (int mt = 0; mt < 4; ++mt) {
                uint32_t o = aoff + (uint32_t)(mt * 16 * ASTR * 2) + kb;
                ldm_x4(ah[mt], sAh_b + o);
                ldm_x4(al[mt], sAl_b + o);
            }
#pragma unroll
            for (int nt = 0; nt < 4; ++nt) {
                uint32_t o = boff + (uint32_t)(nt * 8 * ASTR * 2) + kb;
                ldm_x2(bh[nt], sBh_b + o);
                ldm_x2(bl[nt], sBl_b + o);
            }
#pragma unroll
            for (int mt = 0; mt < 4; ++mt)
#pragma unroll
                for (int nt = 0; nt < 4; ++nt)
                    mma_bf16(acc[mt][nt], ah[mt], bh[nt]);
#pragma unroll
            for (int mt = 0; mt < 4; ++mt)
#pragma unroll
                for (int nt = 0; nt < 4; ++nt)
                    mma_bf16(acc[mt][nt], ah[mt], bl[nt]);
#pragma unroll
            for (int mt = 0; mt < 4; ++mt)
#pragma unroll
                for (int nt = 0; nt < 4; ++nt)
                    mma_bf16(acc[mt][nt], al[mt], bh[nt]);
        }
        __syncthreads();
        if (c + 1 < NCHUNK) {
            STORE_CHUNK();
            __syncthreads();
        }
    }

    // epilogue
    const int which = n0g >> 11;
    const int hh = (n0g & 2047) >> 7;
    float* OUT = (mode == 0) ? ((which == 0) ? g_q : (which == 1) ? g_k : g_v)
                             : Cout;
#pragma unroll
    for (int mt = 0; mt < 4; ++mt) {
#pragma unroll
        for (int nt = 0; nt < 4; ++nt) {
            int rA = m0 + warpM + mt * 16 + (lane >> 2);
            int cc = warpN + nt * 8 + (lane & 3) * 2;
#pragma unroll
            for (int half = 0; half < 2; ++half) {
                int r = rA + half * 8;
                float2 val = make_float2(acc[mt][nt][half * 2],
                                         acc[mt][nt][half * 2 + 1]);
                if (mode == 0) {
                    int b = r >> 11, s = r & 2047;
                    *(float2*)(OUT + (((size_t)b * NHEADS + hh) * SEQ + s) * HDIM
                               + cc) = val;
                } else {
                    *(float2*)(OUT + (size_t)r * DMODEL + n0g + cc) = val;
                }
            }
        }
    }
}

// ---------------- fused RoPE + per-head LayerNorm ----------------------------
__global__ __launch_bounds__(128) void rope_ln_kernel(const float* __restrict__ qw,
                                                      const float* __restrict__ kw) {
    int row  = blockIdx.x * 4 + (threadIdx.x >> 5);
    int lane = threadIdx.x & 31;
    bool is_q = (row < BHS);
    int r2 = is_q ? row : row - BHS;
    float* base = is_q ? g_q : g_k;
    const float* w = is_q ? qw : kw;
    int s = r2 & (SEQ - 1);

    float* ptr = base + (size_t)r2 * HDIM + lane * 4;
    float4 v = *(float4*)ptr;
    int p0 = lane * 2, p1 = lane * 2 + 1;
    float c0 = g_cos[s * 64 + p0], s0 = g_sin[s * 64 + p0];
    float c1 = g_cos[s * 64 + p1], s1 = g_sin[s * 64 + p1];
    float o0 = v.x * c0 - v.y * s0;
    float o1 = v.x * s0 + v.y * c0;
    float o2 = v.z * c1 - v.w * s1;
    float o3 = v.z * s1 + v.w * c1;

    float sum = o0 + o1 + o2 + o3;
#pragma unroll
    for (int m = 16; m; m >>= 1) sum += __shfl_xor_sync(~0u, sum, m);
    float mu = sum * (1.0f / 128.0f);
    float d0 = o0 - mu, d1 = o1 - mu, d2 = o2 - mu, d3 = o3 - mu;
    float ss = d0 * d0 + d1 * d1 + d2 * d2 + d3 * d3;
#pragma unroll
    for (int m = 16; m; m >>= 1) ss += __shfl_xor_sync(~0u, ss, m);
    float rstd = rsqrtf(ss * (1.0f / 128.0f) + 1e-5f);

    float4 wv = *(const float4*)(w + lane * 4);
    v.x = d0 * rstd * wv.x; v.y = d1 * rstd * wv.y;
    v.z = d2 * rstd * wv.z; v.w = d3 * rstd * wv.w;
    *(float4*)ptr = v;
}

// ---------------- windowed flash attention (AQ=128, 512 threads, f32x2) -----
#define AQ 128
#define AK 64
#define KSTR 130
#define PSTR 66
#define ATTN_SMEM ((AQ*KSTR + 2*AK*KSTR + AQ*PSTR) * 4)

__global__ __launch_bounds__(512) void attn_kernel(const int* __restrict__ wptr) {
    extern __shared__ float smf[];
    float* Qs = smf;
    float* Ks = Qs + AQ * KSTR;
    float* Vs = Ks + AK * KSTR;
    float* Ps = Vs + AK * KSTR;

    const int bh = blockIdx.x;
    const int q0 = blockIdx.y * AQ;
    const int W  = *wptr;
    const int tid = threadIdx.x;
    const int tx = tid & 15, ty = tid >> 4;

    const float* qbase = g_q + (size_t)bh * SEQ * HDIM;
    const float* kbase = g_k + (size_t)bh * SEQ * HDIM;
    const float* vbase = g_v + (size_t)bh * SEQ * HDIM;
    const float scale = 0.08838834764831845f;

    for (int idx = tid; idx < AQ * 32; idx += 512) {
        int r = idx >> 5, seg = (idx & 31) << 2;
        float4 qv = *(const float4*)(qbase + (size_t)(q0 + r) * HDIM + seg);
        Qs[r * KSTR + seg + 0] = qv.x * scale;
        Qs[r * KSTR + seg + 1] = qv.y * scale;
        Qs[r * KSTR + seg + 2] = qv.z * scale;
        Qs[r * KSTR + seg + 3] = qv.w * scale;
    }

    u64t o2[4][4];
    float mrow[4], lrow[4];
#pragma unroll
    for (int i = 0; i < 4; ++i) {
        mrow[i] = -1e30f; lrow[i] = 0.f;
#pragma unroll
        for (int u = 0; u < 4; ++u) o2[i][u] = 0ull;
    }

    int t0 = q0 - W; if (t0 < 0) t0 = 0; t0 &= ~(AK - 1);
    const int tend = q0 + AQ - AK;

    for (int kt = t0; kt <= tend; kt += AK) {
        for (int idx = tid; idx < AK * 32; idx += 512) {
            int r = idx >> 5, seg = (idx & 31) << 2;
            float4 kv = *(const float4*)(kbase + (size_t)(kt + r) * HDIM + seg);
            float4 vv = *(const float4*)(vbase + (size_t)(kt + r) * HDIM + seg);
            Ks[r * KSTR + seg + 0] = kv.x; Ks[r * KSTR + seg + 1] = kv.y;
            Ks[r * KSTR + seg + 2] = kv.z; Ks[r * KSTR + seg + 3] = kv.w;
            Vs[r * KSTR + seg + 0] = vv.x; Vs[r * KSTR + seg + 1] = vv.y;
            Vs[r * KSTR + seg + 2] = vv.z; Vs[r * KSTR + seg + 3] = vv.w;
        }
        __syncthreads();

        u64t sc2[4][4] = {};
#pragma unroll 2
        for (int k = 0; k < HDIM; k += 2) {
            u64t a2[4], b2[4];
#pragma unroll
            for (int i = 0; i < 4; ++i)
                a2[i] = *(const u64t*)&Qs[(ty + 32 * i) * KSTR + k];
#pragma unroll
            for (int j = 0; j < 4; ++j)
                b2[j] = *(const u64t*)&Ks[(tx + 16 * j) * KSTR + k];
#pragma unroll
            for (int i = 0; i < 4; ++i)
#pragma unroll
                for (int j = 0; j < 4; ++j)
                    sc2[i][j] = ffma2(a2[i], b2[j], sc2[i][j]);
        }
        float sc[4][4];
#pragma unroll
        for (int i = 0; i < 4; ++i)
#pragma unroll
            for (int j = 0; j < 4; ++j) {
                float2 t = funpack(sc2[i][j]);
                sc[i][j] = t.x + t.y;
            }

#pragma unroll
        for (int i = 0; i < 4; ++i) {
            int qg = q0 + ty + 32 * i;
            float tmax = -1e30f;
            bool valid[4];
#pragma unroll
            for (int j = 0; j < 4; ++j) {
                int kg = kt + tx + 16 * j;
                valid[j] = (kg <= qg) && (kg >= qg - W);
                if (valid[j]) tmax = fmaxf(tmax, sc[i][j]);
            }
#pragma unroll
            for (int m = 8; m; m >>= 1)
                tmax = fmaxf(tmax, __shfl_xor_sync(~0u, tmax, m));
            float mnew = fmaxf(mrow[i], tmax);
            float alpha = __expf(mrow[i] - mnew);
            mrow[i] = mnew;
            lrow[i] *= alpha;
#pragma unroll
            for (int j = 0; j < 4; ++j) {
                float p = valid[j] ? __expf(sc[i][j] - mnew) : 0.f;
                lrow[i] += p;
                Ps[(ty + 32 * i) * PSTR + tx + 16 * j] = p;
            }
            u64t al2 = fdup2(alpha);
#pragma unroll
            for (int u = 0; u < 4; ++u) o2[i][u] = fmul2(o2[i][u], al2);
        }
        __syncthreads();

#pragma unroll 2
        for (int kk = 0; kk < AK; ++kk) {
            u64t pd[4], v2[4];
#pragma unroll
            for (int i = 0; i < 4; ++i)
                pd[i] = fdup2(Ps[(ty + 32 * i) * PSTR + kk]);
#pragma unroll
            for (int u = 0; u < 4; ++u)
                v2[u] = *(const u64t*)&Vs[kk * KSTR + 2 * tx + 32 * u];
#pragma unroll
            for (int i = 0; i < 4; ++i)
#pragma unroll
                for (int u = 0; u < 4; ++u)
                    o2[i][u] = ffma2(pd[i], v2[u], o2[i][u]);
        }
        __syncthreads();
    }

    const int b = bh >> 4, h = bh & 15;
#pragma unroll
    for (int i = 0; i < 4; ++i) {
        float lsum = lrow[i];
#pragma unroll
        for (int m = 8; m; m >>= 1) lsum += __shfl_xor_sync(~0u, lsum, m);
        float inv = 1.0f / lsum;
        int sg = q0 + ty + 32 * i;
        float* orow = g_att + ((size_t)(b * SEQ + sg)) * DMODEL + h * HDIM;
#pragma unroll
        for (int u = 0; u < 4; ++u) {
            float2 t = funpack(o2[i][u]);
            *(float2*)(orow + 2 * tx + 32 * u) = make_float2(t.x * inv, t.y * inv);
        }
    }
}

// ---------------- launch -----------------------------------------------------
extern "C" void kernel_launch(void* const* d_in, const int* in_sizes, int n_in,
                              void* d_out, int out_size) {
    const float* x   = (const float*)d_in[0];
    const float* wq  = (const float*)d_in[1];
    const float* wk  = (const float*)d_in[2];
    const float* wv  = (const float*)d_in[3];
    const float* wo  = (const float*)d_in[4];
    const float* qnw = (const float*)d_in[5];
    const float* knw = (const float*)d_in[6];
    const int*   wsz = (const int*)d_in[7];
    (void)in_sizes; (void)n_in; (void)out_size;

    cudaFuncSetAttribute(attn_kernel,
                         cudaFuncAttributeMaxDynamicSharedMemorySize, ATTN_SMEM);

    rope_table_kernel<<<(SEQ * 64 + 255) / 256, 256>>>();
    gemm_mma<<<dim3(3 * DMODEL / 128, MROWS / 128), 256>>>(
        x, wq, wk, wv, nullptr, 0);
    rope_ln_kernel<<<(2 * BHS) / 4, 128>>>(qnw, knw);
    attn_kernel<<<dim3(BATCH * NHEADS, SEQ / AQ), 512, ATTN_SMEM>>>(wsz);
    gemm_mma<<<dim3(DMODEL / 128, MROWS / 128), 256>>>(
        x /*unused in mode 1*/, wo, nullptr, nullptr, (float*)d_out, 1);
}

// round 6
// speedup vs baseline: 2.2233x; 1.2264x over previous
#include <cuda_runtime.h>
#include <cuda_bf16.h>
#include <math.h>
#include <stdint.h>

#define DMODEL 2048
#define NHEADS 16
#define HDIM   128
#define BATCH  2
#define SEQ    2048
#define MROWS  (BATCH*SEQ)            // 4096
#define BHS    (BATCH*NHEADS*SEQ)     // 65536 rows of HDIM

typedef unsigned long long u64t;

// ---------------- f32x2 helpers (attention kernel) --------------------------
__device__ __forceinline__ u64t ffma2(u64t a, u64t b, u64t c) {
    u64t d; asm("fma.rn.f32x2 %0,%1,%2,%3;" : "=l"(d) : "l"(a), "l"(b), "l"(c));
    return d;
}
__device__ __forceinline__ u64t fmul2(u64t a, u64t b) {
    u64t d; asm("mul.rn.f32x2 %0,%1,%2;" : "=l"(d) : "l"(a), "l"(b));
    return d;
}
__device__ __forceinline__ u64t fdup2(float x) {
    u64t d; asm("mov.b64 %0,{%1,%1};" : "=l"(d) : "f"(x));
    return d;
}
__device__ __forceinline__ float2 funpack(u64t d) {
    float2 r; asm("mov.b64 {%0,%1},%2;" : "=f"(r.x), "=f"(r.y) : "l"(d));
    return r;
}

// ---------------- generic-PTX tensor core / async helpers -------------------
__device__ __forceinline__ uint32_t smem_u32(const void* p) {
    uint32_t a;
    asm("{ .reg .u64 t; cvta.to.shared.u64 t, %1; cvt.u32.u64 %0, t; }"
        : "=r"(a) : "l"(p));
    return a;
}
__device__ __forceinline__ void ldm_x4(uint32_t r[4], uint32_t addr) {
    asm volatile("ldmatrix.sync.aligned.m8n8.x4.shared.b16 {%0,%1,%2,%3}, [%4];"
        : "=r"(r[0]), "=r"(r[1]), "=r"(r[2]), "=r"(r[3]) : "r"(addr));
}
__device__ __forceinline__ void ldm_x2(uint32_t r[2], uint32_t addr) {
    asm volatile("ldmatrix.sync.aligned.m8n8.x2.shared.b16 {%0,%1}, [%2];"
        : "=r"(r[0]), "=r"(r[1]) : "r"(addr));
}
__device__ __forceinline__ void mma_bf16(float c[4], const uint32_t a[4],
                                         const uint32_t b[2]) {
    asm volatile(
        "mma.sync.aligned.m16n8k16.row.col.f32.bf16.bf16.f32 "
        "{%0,%1,%2,%3}, {%4,%5,%6,%7}, {%8,%9}, {%0,%1,%2,%3};"
        : "+f"(c[0]), "+f"(c[1]), "+f"(c[2]), "+f"(c[3])
        : "r"(a[0]), "r"(a[1]), "r"(a[2]), "r"(a[3]), "r"(b[0]), "r"(b[1]));
}
__device__ __forceinline__ void cpa16(uint32_t dst, const void* src) {
    asm volatile("cp.async.ca.shared.global [%0], [%1], 16;"
                 :: "r"(dst), "l"(src) : "memory");
}
#define CP_COMMIT() asm volatile("cp.async.commit_group;" ::: "memory")
#define CP_WAIT1()  asm volatile("cp.async.wait_group 1;" ::: "memory")
#define CP_WAIT0()  asm volatile("cp.async.wait_group 0;" ::: "memory")

// ---------------- scratch ----------------------------------------------------
__device__ float g_q[BHS*HDIM];       // [B][H][S][D] fp32
__device__ float g_k[BHS*HDIM];
__device__ float g_v[BHS*HDIM];
__device__ float g_cos[SEQ*64];
__device__ float g_sin[SEQ*64];
// pre-split bf16 hi/lo operands
__device__ __nv_bfloat16 gxh[MROWS*DMODEL],  gxl[MROWS*DMODEL];
__device__ __nv_bfloat16 gwh[4*DMODEL*DMODEL], gwl[4*DMODEL*DMODEL]; // q,k,v,o
__device__ __nv_bfloat16 gatth[MROWS*DMODEL], gattl[MROWS*DMODEL];

// ---------------- RoPE table -------------------------------------------------
__global__ void rope_table_kernel() {
    int idx = blockIdx.x * 256 + threadIdx.x;
    if (idx >= SEQ * 64) return;
    int s = idx >> 6, p = idx & 63;
    double invf = pow(10000.0, -((double)(2 * p)) / 128.0);
    float invf_f = (float)invf;
    float ang = (float)s * invf_f;
    g_cos[idx] = (float)cos((double)ang);
    g_sin[idx] = (float)sin((double)ang);
}

// ---------------- fp32 -> bf16 hi/lo split pre-pass --------------------------
// sel 0: x -> gxh/gxl ; sel 1..4: w(sel-1) -> gwh/gwl slab
__global__ __launch_bounds__(256) void split_kernel(const float* __restrict__ src,
                                                    int sel, int n4) {
    int i = blockIdx.x * 256 + threadIdx.x;
    if (i >= n4) return;
    __nv_bfloat16 *dh, *dl;
    if (sel == 0) { dh = gxh; dl = gxl; }
    else {
        size_t off = (size_t)(sel - 1) * DMODEL * DMODEL;
        dh = gwh + off; dl = gwl + off;
    }
    float4 f = ((const float4*)src)[i];
    __nv_bfloat16 h0 = __float2bfloat16_rn(f.x), h1 = __float2bfloat16_rn(f.y);
    __nv_bfloat16 h2 = __float2bfloat16_rn(f.z), h3 = __float2bfloat16_rn(f.w);
    __nv_bfloat16 l0 = __float2bfloat16_rn(f.x - __bfloat162float(h0));
    __nv_bfloat16 l1 = __float2bfloat16_rn(f.y - __bfloat162float(h1));
    __nv_bfloat16 l2 = __float2bfloat16_rn(f.z - __bfloat162float(h2));
    __nv_bfloat16 l3 = __float2bfloat16_rn(f.w - __bfloat162float(h3));
    uint2 uh = make_uint2(
        (uint32_t)__bfloat16_as_ushort(h0) | ((uint32_t)__bfloat16_as_ushort(h1) << 16),
        (uint32_t)__bfloat16_as_ushort(h2) | ((uint32_t)__bfloat16_as_ushort(h3) << 16));
    uint2 ul = make_uint2(
        (uint32_t)__bfloat16_as_ushort(l0) | ((uint32_t)__bfloat16_as_ushort(l1) << 16),
        (uint32_t)__bfloat16_as_ushort(l2) | ((uint32_t)__bfloat16_as_ushort(l3) << 16));
    *(uint2*)(dh + 4 * (size_t)i) = uh;
    *(uint2*)(dl + 4 * (size_t)i) = ul;
}

// ---------------- bf16 GEMM, pre-split operands, cp.async double buffer -----
// mode 0: A=gx, B=w[n0g>>11], scatter fp32 to g_q/g_k/g_v
// mode 1: A=gatt, B=w[3] (wo), write Cout fp32 row-major
#define KC 32
#define NCHUNK (DMODEL/KC)     // 64
#define ASTR 40                // bf16 row stride (80B, conflict-free ldmatrix)
#define SARR (128*ASTR*2)      // bytes per operand array: 10240
#define SBUF (4*SARR)          // bytes per buffer: 40960
#define GSMEM (2*SBUF)         // 81920

__global__ __launch_bounds__(256) void gemm_bf16(float* __restrict__ Cout,
                                                 int mode) {
    extern __shared__ __align__(16) char smc[];
    const uint32_t smb = smem_u32(smc);
    const int tid = threadIdx.x;
    const int lane = tid & 31, wid = tid >> 5;
    const int warpM = (wid >> 2) * 64;
    const int warpN = (wid & 3) * 32;

    const int m0  = blockIdx.y * 128;
    const int n0g = blockIdx.x * 128;
    const int slab = (mode == 0) ? (n0g >> 11) : 3;
    const int n0   = (mode == 0) ? (n0g & 2047) : n0g;

    const __nv_bfloat16* Ah = (mode == 0) ? gxh : gatth;
    const __nv_bfloat16* Al = (mode == 0) ? gxl : gattl;
    const __nv_bfloat16* Bh = gwh + (size_t)slab * DMODEL * DMODEL;
    const __nv_bfloat16* Bl = gwl + (size_t)slab * DMODEL * DMODEL;

    // per-chunk async load: 128 rows x 32 bf16 (4x16B segs) per operand array
#define LOAD_CHUNK(c, buf) do {                                                \
    const int c0 = (c) * KC;                                                   \
    const uint32_t bb = smb + (buf) * SBUF;                                    \
    _Pragma("unroll")                                                          \
    for (int i = 0; i < 2; ++i) {                                              \
        int idx = tid + 256 * i;          /* 0..511 */                         \
        int r = idx >> 2, seg = idx & 3;                                       \
        uint32_t d = r * (ASTR * 2) + seg * 16;                                \
        size_t sa = (size_t)(m0 + r) * DMODEL + c0 + seg * 8;                  \
        size_t sb = (size_t)(n0 + r) * DMODEL + c0 + seg * 8;                  \
        cpa16(bb + 0 * SARR + d, Ah + sa);                                     \
        cpa16(bb + 1 * SARR + d, Al + sa);                                     \
        cpa16(bb + 2 * SARR + d, Bh + sb);                                     \
        cpa16(bb + 3 * SARR + d, Bl + sb);                                     \
    } } while (0)

    LOAD_CHUNK(0, 0); CP_COMMIT();
    LOAD_CHUNK(1, 1); CP_COMMIT();

    float acc[4][4][4];
#pragma unroll
    for (int mt = 0; mt < 4; ++mt)
#pragma unroll
        for (int nt = 0; nt < 4; ++nt)
#pragma unroll
            for (int q = 0; q < 4; ++q) acc[mt][nt][q] = 0.f;

    const uint32_t aoff = (uint32_t)(((warpM + (lane & 15)) * ASTR
                                      + (lane >> 4) * 8) * 2);
    const uint32_t boff = (uint32_t)(((warpN + (lane & 7)) * ASTR
                                      + ((lane >> 3) & 1) * 8) * 2);

    for (int c = 0; c < NCHUNK; ++c) {
        const int buf = c & 1;
        if (c + 2 < NCHUNK) CP_WAIT1(); else CP_WAIT0();
        __syncthreads();

        const uint32_t bA_h = smb + buf * SBUF + 0 * SARR;
        const uint32_t bA_l = smb + buf * SBUF + 1 * SARR;
        const uint32_t bB_h = smb + buf * SBUF + 2 * SARR;
        const uint32_t bB_l = smb + buf * SBUF + 3 * SARR;

#pragma unroll
        for (int ks = 0; ks < 2; ++ks) {
            const uint32_t kb = ks * 32;     // 16 bf16 = 32B
            uint32_t ah[4][4], al[4][4], bh[4][2], bl[4][2];
#pragma unroll
            for (int mt = 0; mt < 4; ++mt) {
                uint32_t o = aoff + (uint32_t)(mt * 16 * ASTR * 2) + kb;
                ldm_x4(ah[mt], bA_h + o);
                ldm_x4(al[mt], bA_l + o);
            }
#pragma unroll
            for (int nt = 0; nt < 4; ++nt) {
                uint32_t o = boff + (uint32_t)(nt * 8 * ASTR * 2) + kb;
                ldm_x2(bh[nt], bB_h + o);
                ldm_x2(bl[nt], bB_l + o);
            }
#pragma unroll
            for (int mt = 0; mt < 4; ++mt)
#pragma unroll
                for (int nt = 0; nt < 4; ++nt)
                    mma_bf16(acc[mt][nt], ah[mt], bh[nt]);
#pragma unroll
            for (int mt = 0; mt < 4; ++mt)
#pragma unroll
                for (int nt = 0; nt < 4; ++nt)
                    mma_bf16(acc[mt][nt], ah[mt], bl[nt]);
#pragma unroll
            for (int mt = 0; mt < 4; ++mt)
#pragma unroll
                for (int nt = 0; nt < 4; ++nt)
                    mma_bf16(acc[mt][nt], al[mt], bh[nt]);
        }
        __syncthreads();
        if (c + 2 < NCHUNK) { LOAD_CHUNK(c + 2, buf); CP_COMMIT(); }
    }

    // epilogue
    const int hh = (n0g & 2047) >> 7;
    float* OUT = (mode == 0)
        ? ((slab == 0) ? g_q : (slab == 1) ? g_k : g_v) : Cout;
#pragma unroll
    for (int mt = 0; mt < 4; ++mt) {
#pragma unroll
        for (int nt = 0; nt < 4; ++nt) {
            int rA = m0 + warpM + mt * 16 + (lane >> 2);
            int cc = warpN + nt * 8 + (lane & 3) * 2;
#pragma unroll
            for (int half = 0; half < 2; ++half) {
                int r = rA + half * 8;
                float2 val = make_float2(acc[mt][nt][half * 2],
                                         acc[mt][nt][half * 2 + 1]);
                if (mode == 0) {
                    int b = r >> 11, s = r & 2047;
                    *(float2*)(OUT + (((size_t)b * NHEADS + hh) * SEQ + s) * HDIM
                               + cc) = val;
                } else {
                    *(float2*)(OUT + (size_t)r * DMODEL + n0g + cc) = val;
                }
            }
        }
    }
}

// ---------------- fused RoPE + per-head LayerNorm ----------------------------
__global__ __launch_bounds__(128) void rope_ln_kernel(const float* __restrict__ qw,
                                                      const float* __restrict__ kw) {
    int row  = blockIdx.x * 4 + (threadIdx.x >> 5);
    int lane = threadIdx.x & 31;
    bool is_q = (row < BHS);
    int r2 = is_q ? row : row - BHS;
    float* base = is_q ? g_q : g_k;
    const float* w = is_q ? qw : kw;
    int s = r2 & (SEQ - 1);

    float* ptr = base + (size_t)r2 * HDIM + lane * 4;
    float4 v = *(float4*)ptr;
    int p0 = lane * 2, p1 = lane * 2 + 1;
    float c0 = g_cos[s * 64 + p0], s0 = g_sin[s * 64 + p0];
    float c1 = g_cos[s * 64 + p1], s1 = g_sin[s * 64 + p1];
    float o0 = v.x * c0 - v.y * s0;
    float o1 = v.x * s0 + v.y * c0;
    float o2 = v.z * c1 - v.w * s1;
    float o3 = v.z * s1 + v.w * c1;

    float sum = o0 + o1 + o2 + o3;
#pragma unroll
    for (int m = 16; m; m >>= 1) sum += __shfl_xor_sync(~0u, sum, m);
    float mu = sum * (1.0f / 128.0f);
    float d0 = o0 - mu, d1 = o1 - mu, d2 = o2 - mu, d3 = o3 - mu;
    float ss = d0 * d0 + d1 * d1 + d2 * d2 + d3 * d3;
#pragma unroll
    for (int m = 16; m; m >>= 1) ss += __shfl_xor_sync(~0u, ss, m);
    float rstd = rsqrtf(ss * (1.0f / 128.0f) + 1e-5f);

    float4 wv = *(const float4*)(w + lane * 4);
    v.x = d0 * rstd * wv.x; v.y = d1 * rstd * wv.y;
    v.z = d2 * rstd * wv.z; v.w = d3 * rstd * wv.w;
    *(float4*)ptr = v;
}

// ---------------- windowed flash attention (AQ=128, 512 threads, f32x2) -----
#define AQ 128
#define AK 64
#define KSTR 130
#define PSTR 66
#define ATTN_SMEM ((AQ*KSTR + 2*AK*KSTR + AQ*PSTR) * 4)

__global__ __launch_bounds__(512) void attn_kernel(const int* __restrict__ wptr) {
    extern __shared__ float smf[];
    float* Qs = smf;
    float* Ks = Qs + AQ * KSTR;
    float* Vs = Ks + AK * KSTR;
    float* Ps = Vs + AK * KSTR;

    const int bh = blockIdx.x;
    const int q0 = blockIdx.y * AQ;
    const int W  = *wptr;
    const int tid = threadIdx.x;
    const int tx = tid & 15, ty = tid >> 4;

    const float* qbase = g_q + (size_t)bh * SEQ * HDIM;
    const float* kbase = g_k + (size_t)bh * SEQ * HDIM;
    const float* vbase = g_v + (size_t)bh * SEQ * HDIM;
    const float scale = 0.08838834764831845f;

    for (int idx = tid; idx < AQ * 32; idx += 512) {
        int r = idx >> 5, seg = (idx & 31) << 2;
        float4 qv = *(const float4*)(qbase + (size_t)(q0 + r) * HDIM + seg);
        Qs[r * KSTR + seg + 0] = qv.x * scale;
        Qs[r * KSTR + seg + 1] = qv.y * scale;
        Qs[r * KSTR + seg + 2] = qv.z * scale;
        Qs[r * KSTR + seg + 3] = qv.w * scale;
    }

    u64t o2[4][4];
    float mrow[4], lrow[4];
#pragma unroll
    for (int i = 0; i < 4; ++i) {
        mrow[i] = -1e30f; lrow[i] = 0.f;
#pragma unroll
        for (int u = 0; u < 4; ++u) o2[i][u] = 0ull;
    }

    int t0 = q0 - W; if (t0 < 0) t0 = 0; t0 &= ~(AK - 1);
    const int tend = q0 + AQ - AK;

    for (int kt = t0; kt <= tend; kt += AK) {
        for (int idx = tid; idx < AK * 32; idx += 512) {
            int r = idx >> 5, seg = (idx & 31) << 2;
            float4 kv = *(const float4*)(kbase + (size_t)(kt + r) * HDIM + seg);
            float4 vv = *(const float4*)(vbase + (size_t)(kt + r) * HDIM + seg);
            Ks[r * KSTR + seg + 0] = kv.x; Ks[r * KSTR + seg + 1] = kv.y;
            Ks[r * KSTR + seg + 2] = kv.z; Ks[r * KSTR + seg + 3] = kv.w;
            Vs[r * KSTR + seg + 0] = vv.x; Vs[r * KSTR + seg + 1] = vv.y;
            Vs[r * KSTR + seg + 2] = vv.z; Vs[r * KSTR + seg + 3] = vv.w;
        }
        __syncthreads();

        u64t sc2[4][4] = {};
#pragma unroll 2
        for (int k = 0; k < HDIM; k += 2) {
            u64t a2[4], b2[4];
#pragma unroll
            for (int i = 0; i < 4; ++i)
                a2[i] = *(const u64t*)&Qs[(ty + 32 * i) * KSTR + k];
#pragma unroll
            for (int j = 0; j < 4; ++j)
                b2[j] = *(const u64t*)&Ks[(tx + 16 * j) * KSTR + k];
#pragma unroll
            for (int i = 0; i < 4; ++i)
#pragma unroll
                for (int j = 0; j < 4; ++j)
                    sc2[i][j] = ffma2(a2[i], b2[j], sc2[i][j]);
        }
        float sc[4][4];
#pragma unroll
        for (int i = 0; i < 4; ++i)
#pragma unroll
            for (int j = 0; j < 4; ++j) {
                float2 t = funpack(sc2[i][j]);
                sc[i][j] = t.x + t.y;
            }

#pragma unroll
        for (int i = 0; i < 4; ++i) {
            int qg = q0 + ty + 32 * i;
            float tmax = -1e30f;
            bool valid[4];
#pragma unroll
            for (int j = 0; j < 4; ++j) {
                int kg = kt + tx + 16 * j;
                valid[j] = (kg <= qg) && (kg >= qg - W);
                if (valid[j]) tmax = fmaxf(tmax, sc[i][j]);
            }
#pragma unroll
            for (int m = 8; m; m >>= 1)
                tmax = fmaxf(tmax, __shfl_xor_sync(~0u, tmax, m));
            float mnew = fmaxf(mrow[i], tmax);
            float alpha = __expf(mrow[i] - mnew);
            mrow[i] = mnew;
            lrow[i] *= alpha;
#pragma unroll
            for (int j = 0; j < 4; ++j) {
                float p = valid[j] ? __expf(sc[i][j] - mnew) : 0.f;
                lrow[i] += p;
                Ps[(ty + 32 * i) * PSTR + tx + 16 * j] = p;
            }
            u64t al2 = fdup2(alpha);
#pragma unroll
            for (int u = 0; u < 4; ++u) o2[i][u] = fmul2(o2[i][u], al2);
        }
        __syncthreads();

#pragma unroll 2
        for (int kk = 0; kk < AK; ++kk) {
            u64t pd[4], v2[4];
#pragma unroll
            for (int i = 0; i < 4; ++i)
                pd[i] = fdup2(Ps[(ty + 32 * i) * PSTR + kk]);
#pragma unroll
            for (int u = 0; u < 4; ++u)
                v2[u] = *(const u64t*)&Vs[kk * KSTR + 2 * tx + 32 * u];
#pragma unroll
            for (int i = 0; i < 4; ++i)
#pragma unroll
                for (int u = 0; u < 4; ++u)
                    o2[i][u] = ffma2(pd[i], v2[u], o2[i][u]);
        }
        __syncthreads();
    }

    // epilogue: write attention output directly as bf16 hi/lo split
    const int b = bh >> 4, h = bh & 15;
#pragma unroll
    for (int i = 0; i < 4; ++i) {
        float lsum = lrow[i];
#pragma unroll
        for (int m = 8; m; m >>= 1) lsum += __shfl_xor_sync(~0u, lsum, m);
        float inv = 1.0f / lsum;
        int sg = q0 + ty + 32 * i;
        size_t rowb = ((size_t)(b * SEQ + sg)) * DMODEL + h * HDIM;
#pragma unroll
        for (int u = 0; u < 4; ++u) {
            float2 t = funpack(o2[i][u]);
            float v0 = t.x * inv, v1 = t.y * inv;
            __nv_bfloat16 h0 = __float2bfloat16_rn(v0);
            __nv_bfloat16 h1 = __float2bfloat16_rn(v1);
            __nv_bfloat16 l0 = __float2bfloat16_rn(v0 - __bfloat162float(h0));
            __nv_bfloat16 l1 = __float2bfloat16_rn(v1 - __bfloat162float(h1));
            size_t ix = rowb + 2 * tx + 32 * u;
            *(uint32_t*)&gatth[ix] = (uint32_t)__bfloat16_as_ushort(h0)
                                   | ((uint32_t)__bfloat16_as_ushort(h1) << 16);
            *(uint32_t*)&gattl[ix] = (uint32_t)__bfloat16_as_ushort(l0)
                                   | ((uint32_t)__bfloat16_as_ushort(l1) << 16);
        }
    }
}

// ---------------- launch -----------------------------------------------------
extern "C" void kernel_launch(void* const* d_in, const int* in_sizes, int n_in,
                              void* d_out, int out_size) {
    const float* x   = (const float*)d_in[0];
    const float* wq  = (const float*)d_in[1];
    const float* wk  = (const float*)d_in[2];
    const float* wv  = (const float*)d_in[3];
    const float* wo  = (const float*)d_in[4];
    const float* qnw = (const float*)d_in[5];
    const float* knw = (const float*)d_in[6];
    const int*   wsz = (const int*)d_in[7];
    (void)in_sizes; (void)n_in; (void)out_size;

    cudaFuncSetAttribute(gemm_bf16,
                         cudaFuncAttributeMaxDynamicSharedMemorySize, GSMEM);
    cudaFuncSetAttribute(attn_kernel,
                         cudaFuncAttributeMaxDynamicSharedMemorySize, ATTN_SMEM);

    rope_table_kernel<<<(SEQ * 64 + 255) / 256, 256>>>();

    const int n4x = MROWS * DMODEL / 4;          // 2M float4
    const int n4w = DMODEL * DMODEL / 4;         // 1M float4
    split_kernel<<<(n4x + 255) / 256, 256>>>(x, 0, n4x);
    split_kernel<<<(n4w + 255) / 256, 256>>>(wq, 1, n4w);
    split_kernel<<<(n4w + 255) / 256, 256>>>(wk, 2, n4w);
    split_kernel<<<(n4w + 255) / 256, 256>>>(wv, 3, n4w);
    split_kernel<<<(n4w + 255) / 256, 256>>>(wo, 4, n4w);

    gemm_bf16<<<dim3(3 * DMODEL / 128, MROWS / 128), 256, GSMEM>>>(nullptr, 0);
    rope_ln_kernel<<<(2 * BHS) / 4, 128>>>(qnw, knw);
    attn_kernel<<<dim3(BATCH * NHEADS, SEQ / AQ), 512, ATTN_SMEM>>>(wsz);
    gemm_bf16<<<dim3(DMODEL / 128, MROWS / 128), 256, GSMEM>>>((float*)d_out, 1);
}

// round 9
// speedup vs baseline: 2.9286x; 1.3172x over previous
#include <cuda_runtime.h>
#include <cuda_bf16.h>
#include <math.h>
#include <stdint.h>

#define DMODEL 2048
#define NHEADS 16
#define HDIM   128
#define BATCH  2
#define SEQ    2048
#define MROWS  (BATCH*SEQ)            // 4096
#define BHS    (BATCH*NHEADS*SEQ)     // 65536

typedef unsigned long long u64t;

// ---------------- generic-PTX tensor core / async helpers -------------------
__device__ __forceinline__ uint32_t smem_u32(const void* p) {
    uint32_t a;
    asm("{ .reg .u64 t; cvta.to.shared.u64 t, %1; cvt.u32.u64 %0, t; }"
        : "=r"(a) : "l"(p));
    return a;
}
__device__ __forceinline__ void ldm_x4(uint32_t r[4], uint32_t addr) {
    asm volatile("ldmatrix.sync.aligned.m8n8.x4.shared.b16 {%0,%1,%2,%3}, [%4];"
        : "=r"(r[0]), "=r"(r[1]), "=r"(r[2]), "=r"(r[3]) : "r"(addr));
}
__device__ __forceinline__ void ldm_x2(uint32_t r[2], uint32_t addr) {
    asm volatile("ldmatrix.sync.aligned.m8n8.x2.shared.b16 {%0,%1}, [%2];"
        : "=r"(r[0]), "=r"(r[1]) : "r"(addr));
}
__device__ __forceinline__ void ldm_x2t(uint32_t r[2], uint32_t addr) {
    asm volatile("ldmatrix.sync.aligned.m8n8.x2.trans.shared.b16 {%0,%1}, [%2];"
        : "=r"(r[0]), "=r"(r[1]) : "r"(addr));
}
__device__ __forceinline__ void mma_bf16(float c[4], const uint32_t a[4],
                                         const uint32_t b[2]) {
    asm volatile(
        "mma.sync.aligned.m16n8k16.row.col.f32.bf16.bf16.f32 "
        "{%0,%1,%2,%3}, {%4,%5,%6,%7}, {%8,%9}, {%0,%1,%2,%3};"
        : "+f"(c[0]), "+f"(c[1]), "+f"(c[2]), "+f"(c[3])
        : "r"(a[0]), "r"(a[1]), "r"(a[2]), "r"(a[3]), "r"(b[0]), "r"(b[1]));
}
__device__ __forceinline__ void cpa16(uint32_t dst, const void* src) {
    asm volatile("cp.async.ca.shared.global [%0], [%1], 16;"
                 :: "r"(dst), "l"(src) : "memory");
}
#define CP_COMMIT() asm volatile("cp.async.commit_group;" ::: "memory")
#define CP_WAIT1()  asm volatile("cp.async.wait_group 1;" ::: "memory")
#define CP_WAIT0()  asm volatile("cp.async.wait_group 0;" ::: "memory")

__device__ __forceinline__ uint32_t pack_bf16(float a, float b) {
    __nv_bfloat16 ha = __float2bfloat16_rn(a), hb = __float2bfloat16_rn(b);
    return (uint32_t)__bfloat16_as_ushort(ha)
         | ((uint32_t)__bfloat16_as_ushort(hb) << 16);
}

// ---------------- scratch ----------------------------------------------------
__device__ float g_q[BHS*HDIM];
__device__ float g_k[BHS*HDIM];
__device__ float g_cos[SEQ*64];
__device__ float g_sin[SEQ*64];
__device__ __align__(16) __nv_bfloat16 gxh[MROWS*DMODEL],  gxl[MROWS*DMODEL];
__device__ __align__(16) __nv_bfloat16 gwh[4*DMODEL*DMODEL], gwl[4*DMODEL*DMODEL];
__device__ __align__(16) __nv_bfloat16 gatth[MROWS*DMODEL], gattl[MROWS*DMODEL];
__device__ __align__(16) __nv_bfloat16 gqh[BHS*HDIM], gql[BHS*HDIM];
__device__ __align__(16) __nv_bfloat16 gkh[BHS*HDIM], gkl[BHS*HDIM];
__device__ __align__(16) __nv_bfloat16 gvh[BHS*HDIM], gvl[BHS*HDIM];

// ---------------- RoPE table -------------------------------------------------
__global__ void rope_table_kernel() {
    int idx = blockIdx.x * 256 + threadIdx.x;
    if (idx >= SEQ * 64) return;
    int s = idx >> 6, p = idx & 63;
    double invf = pow(10000.0, -((double)(2 * p)) / 128.0);
    float invf_f = (float)invf;
    float ang = (float)s * invf_f;
    g_cos[idx] = (float)cos((double)ang);
    g_sin[idx] = (float)sin((double)ang);
}

// ---------------- fp32 -> bf16 hi/lo split pre-pass --------------------------
__global__ __launch_bounds__(256) void split_kernel(const float* __restrict__ src,
                                                    int sel, int n4) {
    int i = blockIdx.x * 256 + threadIdx.x;
    if (i >= n4) return;
    __nv_bfloat16 *dh, *dl;
    if (sel == 0) { dh = gxh; dl = gxl; }
    else {
        size_t off = (size_t)(sel - 1) * DMODEL * DMODEL;
        dh = gwh + off; dl = gwl + off;
    }
    float4 f = ((const float4*)src)[i];
    __nv_bfloat16 h0 = __float2bfloat16_rn(f.x), h1 = __float2bfloat16_rn(f.y);
    __nv_bfloat16 h2 = __float2bfloat16_rn(f.z), h3 = __float2bfloat16_rn(f.w);
    uint2 uh = make_uint2(
        (uint32_t)__bfloat16_as_ushort(h0) | ((uint32_t)__bfloat16_as_ushort(h1) << 16),
        (uint32_t)__bfloat16_as_ushort(h2) | ((uint32_t)__bfloat16_as_ushort(h3) << 16));
    uint2 ul = make_uint2(
        pack_bf16(f.x - __bfloat162float(h0), f.y - __bfloat162float(h1)),
        pack_bf16(f.z - __bfloat162float(h2), f.w - __bfloat162float(h3)));
    *(uint2*)(dh + 4 * (size_t)i) = uh;
    *(uint2*)(dl + 4 * (size_t)i) = ul;
}

// ---------------- bf16 GEMM (R6 core, proven) --------------------------------
#define KC 32
#define NCHUNK (DMODEL/KC)
#define ASTR 40
#define SARR (128*ASTR*2)
#define SBUF (4*SARR)
#define GSMEM (2*SBUF)

__global__ __launch_bounds__(256) void gemm_bf16(float* __restrict__ Cout,
                                                 int mode) {
    extern __shared__ __align__(16) char smc[];
    const uint32_t smb = smem_u32(smc);
    const int tid = threadIdx.x;
    const int lane = tid & 31, wid = tid >> 5;
    const int warpM = (wid >> 2) * 64;
    const int warpN = (wid & 3) * 32;

    const int m0  = blockIdx.y * 128;
    const int n0g = blockIdx.x * 128;
    const int slab = (mode == 0) ? (n0g >> 11) : 3;
    const int n0   = (mode == 0) ? (n0g & 2047) : n0g;

    const __nv_bfloat16* Ah = (mode == 0) ? gxh : gatth;
    const __nv_bfloat16* Al = (mode == 0) ? gxl : gattl;
    const __nv_bfloat16* Bh = gwh + (size_t)slab * DMODEL * DMODEL;
    const __nv_bfloat16* Bl = gwl + (size_t)slab * DMODEL * DMODEL;

#define LOAD_CHUNK(c, buf) do {                                                \
    const int c0 = (c) * KC;                                                   \
    const uint32_t bb = smb + (buf) * SBUF;                                    \
    _Pragma("unroll")                                                          \
    for (int i = 0; i < 2; ++i) {                                              \
        int idx = tid + 256 * i;                                               \
        int r = idx >> 2, seg = idx & 3;                                       \
        uint32_t d = r * (ASTR * 2) + seg * 16;                                \
        size_t sa = (size_t)(m0 + r) * DMODEL + c0 + seg * 8;                  \
        size_t sb = (size_t)(n0 + r) * DMODEL + c0 + seg * 8;                  \
        cpa16(bb + 0 * SARR + d, Ah + sa);                                     \
        cpa16(bb + 1 * SARR + d, Al + sa);                                     \
        cpa16(bb + 2 * SARR + d, Bh + sb);                                     \
        cpa16(bb + 3 * SARR + d, Bl + sb);                                     \
    } } while (0)

    LOAD_CHUNK(0, 0); CP_COMMIT();
    LOAD_CHUNK(1, 1); CP_COMMIT();

    float acc[4][4][4];
#pragma unroll
    for (int mt = 0; mt < 4; ++mt)
#pragma unroll
        for (int nt = 0; nt < 4; ++nt)
#pragma unroll
            for (int q = 0; q < 4; ++q) acc[mt][nt][q] = 0.f;

    const uint32_t aoff = (uint32_t)(((warpM + (lane & 15)) * ASTR
                                      + (lane >> 4) * 8) * 2);
    const uint32_t boff = (uint32_t)(((warpN + (lane & 7)) * ASTR
                                      + ((lane >> 3) & 1) * 8) * 2);

    for (int c = 0; c < NCHUNK; ++c) {
        const int buf = c & 1;
        if (c + 2 < NCHUNK) CP_WAIT1(); else CP_WAIT0();
        __syncthreads();

        const uint32_t bA_h = smb + buf * SBUF + 0 * SARR;
        const uint32_t bA_l = smb + buf * SBUF + 1 * SARR;
        const uint32_t bB_h = smb + buf * SBUF + 2 * SARR;
        const uint32_t bB_l = smb + buf * SBUF + 3 * SARR;

#pragma unroll
        for (int ks = 0; ks < 2; ++ks) {
            const uint32_t kb = ks * 32;
            uint32_t ah[4][4], al[4][4], bh[4][2], bl[4][2];
#pragma unroll
            for (int mt = 0; mt < 4; ++mt) {
                uint32_t o = aoff + (uint32_t)(mt * 16 * ASTR * 2) + kb;
                ldm_x4(ah[mt], bA_h + o);
                ldm_x4(al[mt], bA_l + o);
            }
#pragma unroll
            for (int nt = 0; nt < 4; ++nt) {
                uint32_t o = boff + (uint32_t)(nt * 8 * ASTR * 2) + kb;
                ldm_x2(bh[nt], bB_h + o);
                ldm_x2(bl[nt], bB_l + o);
            }
#pragma unroll
            for (int mt = 0; mt < 4; ++mt)
#pragma unroll
                for (int nt = 0; nt < 4; ++nt)
                    mma_bf16(acc[mt][nt], ah[mt], bh[nt]);
#pragma unroll
            for (int mt = 0; mt < 4; ++mt)
#pragma unroll
                for (int nt = 0; nt < 4; ++nt)
                    mma_bf16(acc[mt][nt], ah[mt], bl[nt]);
#pragma unroll
            for (int mt = 0; mt < 4; ++mt)
#pragma unroll
                for (int nt = 0; nt < 4; ++nt)
                    mma_bf16(acc[mt][nt], al[mt], bh[nt]);
        }
        __syncthreads();
        if (c + 2 < NCHUNK) { LOAD_CHUNK(c + 2, buf); CP_COMMIT(); }
    }

    const int hh = (n0g & 2047) >> 7;
#pragma unroll
    for (int mt = 0; mt < 4; ++mt) {
#pragma unroll
        for (int nt = 0; nt < 4; ++nt) {
            int rA = m0 + warpM + mt * 16 + (lane >> 2);
            int cc = warpN + nt * 8 + (lane & 3) * 2;
#pragma unroll
            for (int half = 0; half < 2; ++half) {
                int r = rA + half * 8;
                float2 val = make_float2(acc[mt][nt][half * 2],
                                         acc[mt][nt][half * 2 + 1]);
                if (mode == 0) {
                    int b = r >> 11, s = r & 2047;
                    size_t ix = (((size_t)b * NHEADS + hh) * SEQ + s) * HDIM + cc;
                    if (slab == 2) {
                        __nv_bfloat16 h0 = __float2bfloat16_rn(val.x);
                        __nv_bfloat16 h1 = __float2bfloat16_rn(val.y);
                        *(uint32_t*)&gvh[ix] =
                            (uint32_t)__bfloat16_as_ushort(h0)
                          | ((uint32_t)__bfloat16_as_ushort(h1) << 16);
                        *(uint32_t*)&gvl[ix] = pack_bf16(
                            val.x - __bfloat162float(h0),
                            val.y - __bfloat162float(h1));
                    } else {
                        float* OUT = (slab == 0) ? g_q : g_k;
                        *(float2*)(OUT + ix) = val;
                    }
                } else {
                    *(float2*)(Cout + (size_t)r * DMODEL + n0g + cc) = val;
                }
            }
        }
    }
}

// ---------------- fused RoPE + per-head LayerNorm -> bf16 hi/lo split --------
__global__ __launch_bounds__(128) void rope_ln_kernel(const float* __restrict__ qw,
                                                      const float* __restrict__ kw) {
    int row  = blockIdx.x * 4 + (threadIdx.x >> 5);
    int lane = threadIdx.x & 31;
    bool is_q = (row < BHS);
    int r2 = is_q ? row : row - BHS;
    const float* base = is_q ? g_q : g_k;
    const float* w = is_q ? qw : kw;
    int s = r2 & (SEQ - 1);

    const float* ptr = base + (size_t)r2 * HDIM + lane * 4;
    float4 v = *(const float4*)ptr;
    int p0 = lane * 2, p1 = lane * 2 + 1;
    float c0 = g_cos[s * 64 + p0], s0 = g_sin[s * 64 + p0];
    float c1 = g_cos[s * 64 + p1], s1 = g_sin[s * 64 + p1];
    float o0 = v.x * c0 - v.y * s0;
    float o1 = v.x * s0 + v.y * c0;
    float o2 = v.z * c1 - v.w * s1;
    float o3 = v.z * s1 + v.w * c1;

    float sum = o0 + o1 + o2 + o3;
#pragma unroll
    for (int m = 16; m; m >>= 1) sum += __shfl_xor_sync(~0u, sum, m);
    float mu = sum * (1.0f / 128.0f);
    float d0 = o0 - mu, d1 = o1 - mu, d2 = o2 - mu, d3 = o3 - mu;
    float ss = d0 * d0 + d1 * d1 + d2 * d2 + d3 * d3;
#pragma unroll
    for (int m = 16; m; m >>= 1) ss += __shfl_xor_sync(~0u, ss, m);
    float rstd = rsqrtf(ss * (1.0f / 128.0f) + 1e-5f);
    float scl = is_q ? 0.08838834764831845f : 1.0f;
    rstd *= scl;

    float4 wv = *(const float4*)(w + lane * 4);
    float r0 = d0 * rstd * wv.x, r1 = d1 * rstd * wv.y;
    float r2f = d2 * rstd * wv.z, r3 = d3 * rstd * wv.w;

    __nv_bfloat16* dh = is_q ? gqh : gkh;
    __nv_bfloat16* dl = is_q ? gql : gkl;
    size_t ix = (size_t)r2 * HDIM + lane * 4;
    __nv_bfloat16 h0 = __float2bfloat16_rn(r0), h1 = __float2bfloat16_rn(r1);
    __nv_bfloat16 h2 = __float2bfloat16_rn(r2f), h3 = __float2bfloat16_rn(r3);
    *(uint2*)&dh[ix] = make_uint2(
        (uint32_t)__bfloat16_as_ushort(h0) | ((uint32_t)__bfloat16_as_ushort(h1) << 16),
        (uint32_t)__bfloat16_as_ushort(h2) | ((uint32_t)__bfloat16_as_ushort(h3) << 16));
    *(uint2*)&dl[ix] = make_uint2(
        pack_bf16(r0 - __bfloat162float(h0), r1 - __bfloat162float(h1)),
        pack_bf16(r2f - __bfloat162float(h2), r3 - __bfloat162float(h3)));
}

// ---------------- mma.sync flash attention -----------------------------------
#define QSTRB 272
#define PSTRB 144
#define OQH 0
#define OQL 34816
#define OKH 69632
#define OKL 87040
#define OVH 104448
#define OVL 121856
#define OPH 139264
#define OPL 157696
#define ATTN_SMEM 176128
#define NEGBIG (-1e9f)

__global__ __launch_bounds__(256) void attn_kernel(const int* __restrict__ wptr) {
    extern __shared__ __align__(16) char smc[];
    const uint32_t smb = smem_u32(smc);
    const int tid = threadIdx.x;
    const int lane = tid & 31, wid = tid >> 5;
    const int bh = blockIdx.x;
    const int q0 = blockIdx.y * 128;
    const int W  = *wptr;

    const size_t hb = (size_t)bh * SEQ * HDIM;
    const __nv_bfloat16 *qh = gqh + hb, *ql = gql + hb;
    const __nv_bfloat16 *kh = gkh + hb, *kl = gkl + hb;
    const __nv_bfloat16 *vh = gvh + hb, *vl = gvl + hb;

    // Q tile: 128 rows x 128 bf16 = 16 x 16B segs per row (FIX: was 8)
#pragma unroll
    for (int i = 0; i < 8; ++i) {
        int idx = tid + 256 * i;       // 0..2047
        int r = idx >> 4, seg = idx & 15;
        cpa16(smb + OQH + r * QSTRB + seg * 16,
              qh + (size_t)(q0 + r) * HDIM + seg * 8);
        cpa16(smb + OQL + r * QSTRB + seg * 16,
              ql + (size_t)(q0 + r) * HDIM + seg * 8);
    }
    CP_COMMIT();

    float o[16][4];
#pragma unroll
    for (int v = 0; v < 16; ++v)
#pragma unroll
        for (int q = 0; q < 4; ++q) o[v][q] = 0.f;
    float mrow0 = NEGBIG, mrow1 = NEGBIG, l0 = 0.f, l1 = 0.f;

    const int R0 = q0 + 16 * wid + (lane >> 2);
    const int R1 = R0 + 8;

    int t0 = q0 - W; if (t0 < 0) t0 = 0; t0 &= ~63;
    const int tend = q0 + 64;

    for (int kt = t0; kt <= tend; kt += 64) {
        // K/V tiles: 4 arrays x 64 rows x 16 segs (FIX: was 8 segs)
#pragma unroll
        for (int i = 0; i < 16; ++i) {
            int idx = tid + 256 * i;   // 0..4095
            int arr = idx >> 10, rem = idx & 1023;
            int r = rem >> 4, seg = rem & 15;
            const __nv_bfloat16* src =
                (arr == 0) ? kh : (arr == 1) ? kl : (arr == 2) ? vh : vl;
            cpa16(smb + OKH + arr * 17408 + r * QSTRB + seg * 16,
                  src + (size_t)(kt + r) * HDIM + seg * 8);
        }
        CP_COMMIT();
        CP_WAIT0();
        __syncthreads();

        // ---- S = Q @ K^T ----
        float sc[8][4];
#pragma unroll
        for (int j = 0; j < 8; ++j)
#pragma unroll
            for (int q = 0; q < 4; ++q) sc[j][q] = 0.f;

        const uint32_t aoffQ = (16 * wid + (lane & 15)) * QSTRB
                             + (lane >> 4) * 16;
#pragma unroll
        for (int ks = 0; ks < 8; ++ks) {
            uint32_t ah4[4], al4[4];
            ldm_x4(ah4, smb + OQH + aoffQ + 32 * ks);
            ldm_x4(al4, smb + OQL + aoffQ + 32 * ks);
#pragma unroll
            for (int j = 0; j < 8; ++j) {
                uint32_t kb = (8 * j + (lane & 7)) * QSTRB
                            + ((lane >> 3) & 1) * 16 + 32 * ks;
                uint32_t bh2[2], bl2[2];
                ldm_x2(bh2, smb + OKH + kb);
                ldm_x2(bl2, smb + OKL + kb);
                mma_bf16(sc[j], ah4, bh2);
                mma_bf16(sc[j], ah4, bl2);
                mma_bf16(sc[j], al4, bh2);
            }
        }

        // ---- mask + row max ----
        float mx0 = NEGBIG, mx1 = NEGBIG;
#pragma unroll
        for (int j = 0; j < 8; ++j) {
            int kg = kt + 8 * j + 2 * (lane & 3);
            if (!(kg   <= R0 && kg   >= R0 - W)) sc[j][0] = NEGBIG;
            if (!(kg+1 <= R0 && kg+1 >= R0 - W)) sc[j][1] = NEGBIG;
            if (!(kg   <= R1 && kg   >= R1 - W)) sc[j][2] = NEGBIG;
            if (!(kg+1 <= R1 && kg+1 >= R1 - W)) sc[j][3] = NEGBIG;
            mx0 = fmaxf(mx0, fmaxf(sc[j][0], sc[j][1]));
            mx1 = fmaxf(mx1, fmaxf(sc[j][2], sc[j][3]));
        }
        mx0 = fmaxf(mx0, __shfl_xor_sync(~0u, mx0, 1));
        mx0 = fmaxf(mx0, __shfl_xor_sync(~0u, mx0, 2));
        mx1 = fmaxf(mx1, __shfl_xor_sync(~0u, mx1, 1));
        mx1 = fmaxf(mx1, __shfl_xor_sync(~0u, mx1, 2));

        float mn0 = fmaxf(mrow0, mx0), mn1 = fmaxf(mrow1, mx1);
        float a0 = __expf(fminf(mrow0 - mn0, 0.f));
        float a1 = __expf(fminf(mrow1 - mn1, 0.f));
        mrow0 = mn0; mrow1 = mn1;
        l0 *= a0; l1 *= a1;
#pragma unroll
        for (int v = 0; v < 16; ++v) {
            o[v][0] *= a0; o[v][1] *= a0; o[v][2] *= a1; o[v][3] *= a1;
        }

        // ---- P = exp(S-m) ----
        const uint32_t pb0 = OPH + (16 * wid + (lane >> 2)) * PSTRB
                           + 4 * (lane & 3);
#pragma unroll
        for (int j = 0; j < 8; ++j) {
            int kg = kt + 8 * j + 2 * (lane & 3);
            bool v0 = (kg   <= R0 && kg   >= R0 - W);
            bool v1 = (kg+1 <= R0 && kg+1 >= R0 - W);
            bool v2 = (kg   <= R1 && kg   >= R1 - W);
            bool v3 = (kg+1 <= R1 && kg+1 >= R1 - W);
            float p0 = v0 ? __expf(fminf(sc[j][0] - mn0, 0.f)) : 0.f;
            float p1 = v1 ? __expf(fminf(sc[j][1] - mn0, 0.f)) : 0.f;
            float p2 = v2 ? __expf(fminf(sc[j][2] - mn1, 0.f)) : 0.f;
            float p3 = v3 ? __expf(fminf(sc[j][3] - mn1, 0.f)) : 0.f;
            l0 += p0 + p1; l1 += p2 + p3;
            __nv_bfloat16 h0 = __float2bfloat16_rn(p0);
            __nv_bfloat16 h1 = __float2bfloat16_rn(p1);
            __nv_bfloat16 h2 = __float2bfloat16_rn(p2);
            __nv_bfloat16 h3 = __float2bfloat16_rn(p3);
            uint32_t cb = 16 * j;
            *(uint32_t*)(smc + pb0 + cb) =
                (uint32_t)__bfloat16_as_ushort(h0)
              | ((uint32_t)__bfloat16_as_ushort(h1) << 16);
            *(uint32_t*)(smc + pb0 + 8 * PSTRB + cb) =
                (uint32_t)__bfloat16_as_ushort(h2)
              | ((uint32_t)__bfloat16_as_ushort(h3) << 16);
            *(uint32_t*)(smc + pb0 + (OPL - OPH) + cb) =
                pack_bf16(p0 - __bfloat162float(h0), p1 - __bfloat162float(h1));
            *(uint32_t*)(smc + pb0 + (OPL - OPH) + 8 * PSTRB + cb) =
                pack_bf16(p2 - __bfloat162float(h2), p3 - __bfloat162float(h3));
        }
        __syncthreads();

        // ---- O += P @ V ----
        const uint32_t paoff = (16 * wid + (lane & 15)) * PSTRB
                             + (lane >> 4) * 16;
#pragma unroll
        for (int ks2 = 0; ks2 < 4; ++ks2) {
            uint32_t ph4[4], pl4[4];
            ldm_x4(ph4, smb + OPH + paoff + 32 * ks2);
            ldm_x4(pl4, smb + OPL + paoff + 32 * ks2);
#pragma unroll
            for (int v = 0; v < 16; ++v) {
                uint32_t vb = (16 * ks2 + (lane & 15)) * QSTRB + 16 * v;
                uint32_t vh2[2], vl2[2];
                ldm_x2t(vh2, smb + OVH + vb);
                ldm_x2t(vl2, smb + OVL + vb);
                mma_bf16(o[v], ph4, vh2);
                mma_bf16(o[v], ph4, vl2);
                mma_bf16(o[v], pl4, vh2);
            }
        }
        __syncthreads();
    }

    // ---- finalize ----
    l0 += __shfl_xor_sync(~0u, l0, 1); l0 += __shfl_xor_sync(~0u, l0, 2);
    l1 += __shfl_xor_sync(~0u, l1, 1); l1 += __shfl_xor_sync(~0u, l1, 2);
    float inv0 = 1.0f / fmaxf(l0, 1e-30f);
    float inv1 = 1.0f / fmaxf(l1, 1e-30f);

    const int b = bh >> 4, h = bh & 15;
    const size_t rb0 = ((size_t)(b * SEQ + R0)) * DMODEL + h * HDIM;
    const size_t rb1 = ((size_t)(b * SEQ + R1)) * DMODEL + h * HDIM;
#pragma unroll
    for (int v = 0; v < 16; ++v) {
        int c = 8 * v + 2 * (lane & 3);
        float x0 = o[v][0] * inv0, x1 = o[v][1] * inv0;
        float x2 = o[v][2] * inv1, x3 = o[v][3] * inv1;
        __nv_bfloat16 h0 = __float2bfloat16_rn(x0);
        __nv_bfloat16 h1 = __float2bfloat16_rn(x1);
        __nv_bfloat16 h2 = __float2bfloat16_rn(x2);
        __nv_bfloat16 h3 = __float2bfloat16_rn(x3);
        *(uint32_t*)&gatth[rb0 + c] =
            (uint32_t)__bfloat16_as_ushort(h0)
          | ((uint32_t)__bfloat16_as_ushort(h1) << 16);
        *(uint32_t*)&gatth[rb1 + c] =
            (uint32_t)__bfloat16_as_ushort(h2)
          | ((uint32_t)__bfloat16_as_ushort(h3) << 16);
        *(uint32_t*)&gattl[rb0 + c] =
            pack_bf16(x0 - __bfloat162float(h0), x1 - __bfloat162float(h1));
        *(uint32_t*)&gattl[rb1 + c] =
            pack_bf16(x2 - __bfloat162float(h2), x3 - __bfloat162float(h3));
    }
}

// ---------------- launch -----------------------------------------------------
extern "C" void kernel_launch(void* const* d_in, const int* in_sizes, int n_in,
                              void* d_out, int out_size) {
    const float* x   = (const float*)d_in[0];
    const float* wq  = (const float*)d_in[1];
    const float* wk  = (const float*)d_in[2];
    const float* wv  = (const float*)d_in[3];
    const float* wo  = (const float*)d_in[4];
    const float* qnw = (const float*)d_in[5];
    const float* knw = (const float*)d_in[6];
    const int*   wsz = (const int*)d_in[7];
    (void)in_sizes; (void)n_in; (void)out_size;

    cudaFuncSetAttribute(gemm_bf16,
                         cudaFuncAttributeMaxDynamicSharedMemorySize, GSMEM);
    cudaFuncSetAttribute(attn_kernel,
                         cudaFuncAttributeMaxDynamicSharedMemorySize, ATTN_SMEM);

    rope_table_kernel<<<(SEQ * 64 + 255) / 256, 256>>>();

    const int n4x = MROWS * DMODEL / 4;
    const int n4w = DMODEL * DMODEL / 4;
    split_kernel<<<(n4x + 255) / 256, 256>>>(x, 0, n4x);
    split_kernel<<<(n4w + 255) / 256, 256>>>(wq, 1, n4w);
    split_kernel<<<(n4w + 255) / 256, 256>>>(wk, 2, n4w);
    split_kernel<<<(n4w + 255) / 256, 256>>>(wv, 3, n4w);
    split_kernel<<<(n4w + 255) / 256, 256>>>(wo, 4, n4w);

    gemm_bf16<<<dim3(3 * DMODEL / 128, MROWS / 128), 256, GSMEM>>>(nullptr, 0);
    rope_ln_kernel<<<(2 * BHS) / 4, 128>>>(qnw, knw);
    attn_kernel<<<dim3(BATCH * NHEADS, SEQ / 128), 256, ATTN_SMEM>>>(wsz);
    gemm_bf16<<<dim3(DMODEL / 128, MROWS / 128), 256, GSMEM>>>((float*)d_out, 1);
}